// round 2
// baseline (speedup 1.0000x reference)
#include <cuda_runtime.h>
#include <cuda_bf16.h>

typedef unsigned long long ull;

#define NB 128
#define NL 512
#define NE 256
#define NH 256
#define NT 16

// ---------------- device scratch (no runtime allocation) ----------------
__device__ float d_x[(size_t)65536 * 256];            // gathered embeddings [m][256], m = l*128+b
__device__ float d_gx[(size_t)2 * 65536 * 1024];      // input gate preacts [dir][m][1024]
__device__ float d_hcat[(size_t)128 * 512 * 512];     // [b][l][hf|hb]
__device__ float d_emission[(size_t)65536 * 16];      // [b*512+l][16]
__device__ __nv_bfloat16 d_whh[2 * 1024 * 256];       // bf16 W_hh [dir][row][k]
__device__ double d_acc[2];                           // [all_path, golden]

// ---------------- f32x2 helpers ----------------
__device__ __forceinline__ ull fma2(ull a, ull b, ull c) {
    ull d; asm("fma.rn.f32x2 %0,%1,%2,%3;" : "=l"(d) : "l"(a), "l"(b), "l"(c)); return d;
}
__device__ __forceinline__ ull pack2f(float x, float y) {
    ull r; asm("mov.b64 %0,{%1,%2};" : "=l"(r) : "f"(x), "f"(y)); return r;
}
__device__ __forceinline__ float2 unpack2(ull v) {
    float x, y; asm("mov.b64 {%0,%1},%2;" : "=f"(x), "=f"(y) : "l"(v));
    float2 r; r.x = x; r.y = y; return r;
}
// one u32 holding 2 bf16 -> packed f32x2
__device__ __forceinline__ ull bf2f2(unsigned w) {
    unsigned lo = w << 16, hi = w & 0xffff0000u;
    ull r; asm("mov.b64 %0,{%1,%2};" : "=l"(r) : "r"(lo), "r"(hi)); return r;
}
__device__ __forceinline__ float sigf(float x) { return 1.f / (1.f + __expf(-x)); }
__device__ __forceinline__ float tanhx(float x) { return 2.f / (1.f + __expf(-2.f * x)) - 1.f; }

// ---------------- K0: prep (bf16 weights, zero accumulators) ----------------
__global__ void k_prep(const float* __restrict__ whf, const float* __restrict__ whb) {
    int i = blockIdx.x * 256 + threadIdx.x;   // grid 2048*256 = 524288
    if (i < 262144) d_whh[i] = __float2bfloat16(whf[i]);
    else            d_whh[i] = __float2bfloat16(whb[i - 262144]);
    if (i < 2) d_acc[i] = 0.0;
}

// ---------------- K1a: embedding gather ----------------
__global__ void k_gather(const int* __restrict__ bd, const float* __restrict__ emb) {
    int m = blockIdx.x * 8 + (threadIdx.x >> 5);
    int lane = threadIdx.x & 31;
    int b = m & 127, l = m >> 7;
    int idx = bd[b * 512 + l];
    const float4* src = (const float4*)(emb + (size_t)idx * 256);
    float4* dst = (float4*)(d_x + (size_t)m * 256);
    dst[lane] = src[lane];
    dst[lane + 32] = src[lane + 32];
}

// ---------------- K1b: input projection SGEMM (f32x2) ----------------
// C[65536][2048] = d_x @ W^T + bias ; n<1024 -> (w_ih_f,b_f), else (w_ih_b,b_b)
__global__ void __launch_bounds__(256) k_gemm(const float* __restrict__ wf,
                                              const float* __restrict__ wb,
                                              const float* __restrict__ bf,
                                              const float* __restrict__ bb) {
    __shared__ float As[16][128];
    __shared__ float Bs[16][128];
    int tid = threadIdx.x;
    int m0 = blockIdx.x * 128;
    int n0 = blockIdx.y * 128;
    int dir = n0 >> 10;
    int nloc0 = n0 & 1023;
    const float* W  = dir ? wb : wf;
    const float* Bv = dir ? bb : bf;

    int lm = tid >> 1;            // 0..127
    int lk = (tid & 1) * 8;       // 0 or 8
    int tm = (tid & 15) * 8;      // m-offset of 8-row micro tile
    int tn = (tid >> 4) * 8;      // n-offset of 8-col micro tile

    float bias[8];
#pragma unroll
    for (int j = 0; j < 8; j++) bias[j] = Bv[nloc0 + tn + j];

    ull acc[4][8];
#pragma unroll
    for (int i = 0; i < 4; i++)
#pragma unroll
        for (int j = 0; j < 8; j++) acc[i][j] = 0ull;

    for (int k0 = 0; k0 < 256; k0 += 16) {
        float4 a0 = *(const float4*)(d_x + (size_t)(m0 + lm) * 256 + k0 + lk);
        float4 a1 = *(const float4*)(d_x + (size_t)(m0 + lm) * 256 + k0 + lk + 4);
        float4 b0 = *(const float4*)(W + (size_t)(nloc0 + lm) * 256 + k0 + lk);
        float4 b1 = *(const float4*)(W + (size_t)(nloc0 + lm) * 256 + k0 + lk + 4);
        __syncthreads();
        As[lk + 0][lm] = a0.x; As[lk + 1][lm] = a0.y; As[lk + 2][lm] = a0.z; As[lk + 3][lm] = a0.w;
        As[lk + 4][lm] = a1.x; As[lk + 5][lm] = a1.y; As[lk + 6][lm] = a1.z; As[lk + 7][lm] = a1.w;
        Bs[lk + 0][lm] = b0.x; Bs[lk + 1][lm] = b0.y; Bs[lk + 2][lm] = b0.z; Bs[lk + 3][lm] = b0.w;
        Bs[lk + 4][lm] = b1.x; Bs[lk + 5][lm] = b1.y; Bs[lk + 6][lm] = b1.z; Bs[lk + 7][lm] = b1.w;
        __syncthreads();
#pragma unroll
        for (int k = 0; k < 16; k++) {
            ull a2[4];
#pragma unroll
            for (int i = 0; i < 4; i++) a2[i] = *(const ull*)&As[k][tm + 2 * i];
            float4 w0 = *(const float4*)&Bs[k][tn];
            float4 w1 = *(const float4*)&Bs[k][tn + 4];
            ull b2[8];
            b2[0] = pack2f(w0.x, w0.x); b2[1] = pack2f(w0.y, w0.y);
            b2[2] = pack2f(w0.z, w0.z); b2[3] = pack2f(w0.w, w0.w);
            b2[4] = pack2f(w1.x, w1.x); b2[5] = pack2f(w1.y, w1.y);
            b2[6] = pack2f(w1.z, w1.z); b2[7] = pack2f(w1.w, w1.w);
#pragma unroll
            for (int i = 0; i < 4; i++)
#pragma unroll
                for (int j = 0; j < 8; j++) acc[i][j] = fma2(a2[i], b2[j], acc[i][j]);
        }
    }
    // epilogue: rows (m0+tm+2i, +1), cols nloc0+tn..+7
#pragma unroll
    for (int i = 0; i < 4; i++) {
        float r0[8], r1[8];
#pragma unroll
        for (int j = 0; j < 8; j++) {
            float2 p = unpack2(acc[i][j]);
            r0[j] = p.x + bias[j];
            r1[j] = p.y + bias[j];
        }
        float* p0 = d_gx + ((size_t)dir * 65536 + (m0 + tm + 2 * i)) * 1024 + nloc0 + tn;
        float* p1 = p0 + 1024;
        *(float4*)(p0)     = make_float4(r0[0], r0[1], r0[2], r0[3]);
        *(float4*)(p0 + 4) = make_float4(r0[4], r0[5], r0[6], r0[7]);
        *(float4*)(p1)     = make_float4(r1[0], r1[1], r1[2], r1[3]);
        *(float4*)(p1 + 4) = make_float4(r1[4], r1[5], r1[6], r1[7]);
    }
}

// ---------------- K2: LSTM recurrence ----------------
// grid 64: blockIdx>>5 = dir, (blockIdx&31)*4 = first batch row. 256 threads = h-dims.
__global__ void __launch_bounds__(256, 1) k_recur() {
    int tid = threadIdx.x;
    int dir = blockIdx.x >> 5;
    int b0 = (blockIdx.x & 31) * 4;
    const __nv_bfloat16* W = d_whh + (size_t)dir * 1024 * 256;
    const uint4* wrow[4];
#pragma unroll
    for (int g = 0; g < 4; g++)
        wrow[g] = (const uint4*)(W + (size_t)(g * 256 + tid) * 256);

    __shared__ float sh[4][256];
    float c_[4], hnew[4];
#pragma unroll
    for (int b = 0; b < 4; b++) { sh[b][tid] = 0.f; c_[b] = 0.f; }
    __syncthreads();

    const float* gxbase = d_gx + (size_t)dir * 65536 * 1024;

    for (int step = 0; step < 512; step++) {
        int l = dir ? (511 - step) : step;
        // prefetch gate-input preacts (hide LDG latency behind the matvec)
        float gxv[4][4];
#pragma unroll
        for (int b = 0; b < 4; b++) {
            const float* gxp = gxbase + (size_t)(l * 128 + b0 + b) * 1024 + tid;
            gxv[b][0] = gxp[0]; gxv[b][1] = gxp[256];
            gxv[b][2] = gxp[512]; gxv[b][3] = gxp[768];
        }
        ull acc[4][4];
#pragma unroll
        for (int g = 0; g < 4; g++)
#pragma unroll
            for (int b = 0; b < 4; b++) acc[g][b] = 0ull;

#pragma unroll 2
        for (int ch = 0; ch < 32; ch++) {
            uint4 a[4];
#pragma unroll
            for (int g = 0; g < 4; g++) a[g] = wrow[g][ch];
            ull w2[4][4];
#pragma unroll
            for (int g = 0; g < 4; g++) {
                w2[g][0] = bf2f2(a[g].x); w2[g][1] = bf2f2(a[g].y);
                w2[g][2] = bf2f2(a[g].z); w2[g][3] = bf2f2(a[g].w);
            }
#pragma unroll
            for (int b = 0; b < 4; b++) {
                const ull* hp = (const ull*)&sh[b][ch * 8];
                ull h0 = hp[0], h1 = hp[1], h2 = hp[2], h3 = hp[3];
#pragma unroll
                for (int g = 0; g < 4; g++) {
                    acc[g][b] = fma2(w2[g][0], h0, acc[g][b]);
                    acc[g][b] = fma2(w2[g][1], h1, acc[g][b]);
                    acc[g][b] = fma2(w2[g][2], h2, acc[g][b]);
                    acc[g][b] = fma2(w2[g][3], h3, acc[g][b]);
                }
            }
        }
        __syncthreads();   // everyone done reading sh for this step
#pragma unroll
        for (int b = 0; b < 4; b++) {
            float2 p;
            p = unpack2(acc[0][b]); float pi = p.x + p.y + gxv[b][0];
            p = unpack2(acc[1][b]); float pf = p.x + p.y + gxv[b][1];
            p = unpack2(acc[2][b]); float pg = p.x + p.y + gxv[b][2];
            p = unpack2(acc[3][b]); float po = p.x + p.y + gxv[b][3];
            float i_ = sigf(pi), f_ = sigf(pf), g_ = tanhx(pg), o_ = sigf(po);
            c_[b] = f_ * c_[b] + i_ * g_;
            float hv = o_ * tanhx(c_[b]);
            hnew[b] = hv;
            d_hcat[((size_t)(b0 + b) * 512 + l) * 512 + dir * 256 + tid] = hv;
        }
#pragma unroll
        for (int b = 0; b < 4; b++) sh[b][tid] = hnew[b];
        __syncthreads();
    }
}

// ---------------- K3: emission = hcat @ w_cls^T + b_cls ----------------
__global__ void __launch_bounds__(256) k_emis(const float* __restrict__ wcls,
                                              const float* __restrict__ bcls) {
    __shared__ float wc[16 * 512];
    int tid = threadIdx.x;
    for (int i = tid; i < 16 * 512 / 4; i += 256)
        ((float4*)wc)[i] = ((const float4*)wcls)[i];
    __syncthreads();
    int m = blockIdx.x * 8 + (tid >> 5);
    int lane = tid & 31;
    float acc[16];
#pragma unroll
    for (int t = 0; t < 16; t++) acc[t] = 0.f;
    const float* hp = d_hcat + (size_t)m * 512;
#pragma unroll
    for (int it = 0; it < 4; it++) {
        int k = it * 128 + lane * 4;
        float4 h4 = *(const float4*)(hp + k);
#pragma unroll
        for (int t = 0; t < 16; t++) {
            float4 w4 = *(const float4*)(wc + t * 512 + k);
            acc[t] += h4.x * w4.x + h4.y * w4.y + h4.z * w4.z + h4.w * w4.w;
        }
    }
#pragma unroll
    for (int t = 0; t < 16; t++)
#pragma unroll
        for (int off = 16; off; off >>= 1) acc[t] += __shfl_xor_sync(0xffffffffu, acc[t], off);
    if (lane < 16) {
        float v = acc[0];
#pragma unroll
        for (int t = 1; t < 16; t++) v = (lane == t) ? acc[t] : v;
        d_emission[(size_t)m * 16 + lane] = v + bcls[lane];
    }
}

// ---------------- K4: CRF golden + forward (1 warp / batch row) ----------------
__global__ void k_crf(const int* __restrict__ tag, const float* __restrict__ trans) {
    __shared__ float tr[256];
    int b = blockIdx.x, lane = threadIdx.x;
    for (int i = lane; i < 256; i += 32) tr[i] = trans[i];
    __syncwarp();
    int cur = lane & 15;
    float tcol[16];
#pragma unroll
    for (int p = 0; p < 16; p++) tcol[p] = tr[p * 16 + cur];
    const int* tg = tag + b * 512;
    int len = 0;
    for (int l2 = lane; l2 < 512; l2 += 32) len += (tg[l2] != 0);
#pragma unroll
    for (int off = 16; off; off >>= 1) len += __shfl_xor_sync(0xffffffffu, len, off);

    const float* em = d_emission + (size_t)b * 512 * 16;
    float gsum = 0.f;
    for (int l2 = lane; l2 < 512; l2 += 32)
        if (l2 < len) {
            int t = tg[l2];
            int pv = l2 ? tg[l2 - 1] : 14;       // START=14
            gsum += em[l2 * 16 + t] + tr[pv * 16 + t];
        }
#pragma unroll
    for (int off = 16; off; off >>= 1) gsum += __shfl_xor_sync(0xffffffffu, gsum, off);

    float score = em[cur] + tr[14 * 16 + cur];   // init: trans[START][cur] + emission[0][cur]
    for (int t = 1; t < 512; t++) {
        float m = -1e30f, s = 0.f;
#pragma unroll
        for (int p = 0; p < 16; p++) {
            float v = __shfl_sync(0xffffffffu, score, p) + tcol[p];
            float mn = fmaxf(m, v);
            s = s * __expf(m - mn) + __expf(v - mn);
            m = mn;
        }
        float ns = em[t * 16 + cur] + m + __logf(s);
        score = (t < len) ? ns : score;
    }
    if (lane == 15) atomicAdd(&d_acc[0], (double)score);  // END=15
    if (lane == 0)  atomicAdd(&d_acc[1], (double)gsum);
}

__global__ void k_final(float* out) {
    out[0] = (float)((d_acc[0] - d_acc[1]) / 128.0);
}

// ---------------- launch ----------------
extern "C" void kernel_launch(void* const* d_in, const int* in_sizes, int n_in,
                              void* d_out, int out_size) {
    const int*   batch_data = (const int*)d_in[0];
    const int*   batch_tag  = (const int*)d_in[1];
    const float* emb        = (const float*)d_in[2];
    const float* w_ih_f     = (const float*)d_in[3];
    const float* w_hh_f     = (const float*)d_in[4];
    const float* b_f        = (const float*)d_in[5];
    const float* w_ih_b     = (const float*)d_in[6];
    const float* w_hh_b     = (const float*)d_in[7];
    const float* b_b        = (const float*)d_in[8];
    const float* w_cls      = (const float*)d_in[9];
    const float* b_cls      = (const float*)d_in[10];
    const float* transition = (const float*)d_in[11];

    k_prep<<<2048, 256>>>(w_hh_f, w_hh_b);
    k_gather<<<8192, 256>>>(batch_data, emb);
    k_gemm<<<dim3(512, 16), 256>>>(w_ih_f, w_ih_b, b_f, b_b);
    k_recur<<<64, 256>>>();
    k_emis<<<8192, 256>>>(w_cls, b_cls);
    k_crf<<<128, 32>>>(batch_tag, transition);
    k_final<<<1, 1>>>((float*)d_out);
}

// round 3
// speedup vs baseline: 1.7527x; 1.7527x over previous
#include <cuda_runtime.h>
#include <cuda_bf16.h>

typedef unsigned long long ull;

// ---------------- device scratch (no runtime allocation) ----------------
__device__ float d_x[(size_t)65536 * 256];            // gathered embeddings [m][256], m = l*128+b
__device__ float d_gx[(size_t)2 * 65536 * 1024];      // input gate preacts [dir][m][1024]
__device__ float d_hcat[(size_t)128 * 512 * 512];     // [b][l][hf|hb]
__device__ float d_emission[(size_t)65536 * 16];      // [b*512+l][16]
__device__ __nv_bfloat16 d_whh[2 * 32 * 1024 * 8];    // bf16 W_hh transposed: [dir][ch][row][8]
__device__ double d_acc[2];                           // [all_path, golden]

// ---------------- f32x2 helpers ----------------
__device__ __forceinline__ ull fma2(ull a, ull b, ull c) {
    ull d; asm("fma.rn.f32x2 %0,%1,%2,%3;" : "=l"(d) : "l"(a), "l"(b), "l"(c)); return d;
}
__device__ __forceinline__ ull pack2f(float x, float y) {
    ull r; asm("mov.b64 %0,{%1,%2};" : "=l"(r) : "f"(x), "f"(y)); return r;
}
__device__ __forceinline__ float2 unpack2(ull v) {
    float x, y; asm("mov.b64 {%0,%1},%2;" : "=f"(x), "=f"(y) : "l"(v));
    float2 r; r.x = x; r.y = y; return r;
}
// one u32 holding 2 bf16 -> packed f32x2
__device__ __forceinline__ ull bf2f2(unsigned w) {
    unsigned lo = w << 16, hi = w & 0xffff0000u;
    ull r; asm("mov.b64 %0,{%1,%2};" : "=l"(r) : "r"(lo), "r"(hi)); return r;
}
__device__ __forceinline__ float sigf(float x) { return 1.f / (1.f + __expf(-x)); }
__device__ __forceinline__ float tanhx(float x) { return 2.f / (1.f + __expf(-2.f * x)) - 1.f; }

// ---------------- K0: prep (bf16 transposed weights, zero accumulators) ----------------
__global__ void k_prep(const float* __restrict__ whf, const float* __restrict__ whb) {
    int e = blockIdx.x * 256 + threadIdx.x;   // 0..524287
    int dir = e >> 18;
    int rem = e & 262143;
    int row = rem >> 8, k = rem & 255;
    const float* src = dir ? whb : whf;
    int ch = k >> 3, jj = k & 7;
    d_whh[((size_t)(dir * 32 + ch) * 1024 + row) * 8 + jj] = __float2bfloat16(src[row * 256 + k]);
    if (e < 2) d_acc[e] = 0.0;
}

// ---------------- K1a: embedding gather ----------------
__global__ void k_gather(const int* __restrict__ bd, const float* __restrict__ emb) {
    int m = blockIdx.x * 8 + (threadIdx.x >> 5);
    int lane = threadIdx.x & 31;
    int b = m & 127, l = m >> 7;
    int idx = bd[b * 512 + l];
    const float4* src = (const float4*)(emb + (size_t)idx * 256);
    float4* dst = (float4*)(d_x + (size_t)m * 256);
    dst[lane] = src[lane];
    dst[lane + 32] = src[lane + 32];
}

// ---------------- K1b: input projection SGEMM (f32x2) ----------------
__global__ void __launch_bounds__(256) k_gemm(const float* __restrict__ wf,
                                              const float* __restrict__ wb,
                                              const float* __restrict__ bf,
                                              const float* __restrict__ bb) {
    __shared__ float As[16][128];
    __shared__ float Bs[16][128];
    int tid = threadIdx.x;
    int m0 = blockIdx.x * 128;
    int n0 = blockIdx.y * 128;
    int dir = n0 >> 10;
    int nloc0 = n0 & 1023;
    const float* W  = dir ? wb : wf;
    const float* Bv = dir ? bb : bf;

    int lm = tid >> 1;
    int lk = (tid & 1) * 8;
    int tm = (tid & 15) * 8;
    int tn = (tid >> 4) * 8;

    float bias[8];
#pragma unroll
    for (int j = 0; j < 8; j++) bias[j] = Bv[nloc0 + tn + j];

    ull acc[4][8];
#pragma unroll
    for (int i = 0; i < 4; i++)
#pragma unroll
        for (int j = 0; j < 8; j++) acc[i][j] = 0ull;

    for (int k0 = 0; k0 < 256; k0 += 16) {
        float4 a0 = *(const float4*)(d_x + (size_t)(m0 + lm) * 256 + k0 + lk);
        float4 a1 = *(const float4*)(d_x + (size_t)(m0 + lm) * 256 + k0 + lk + 4);
        float4 b0 = *(const float4*)(W + (size_t)(nloc0 + lm) * 256 + k0 + lk);
        float4 b1 = *(const float4*)(W + (size_t)(nloc0 + lm) * 256 + k0 + lk + 4);
        __syncthreads();
        As[lk + 0][lm] = a0.x; As[lk + 1][lm] = a0.y; As[lk + 2][lm] = a0.z; As[lk + 3][lm] = a0.w;
        As[lk + 4][lm] = a1.x; As[lk + 5][lm] = a1.y; As[lk + 6][lm] = a1.z; As[lk + 7][lm] = a1.w;
        Bs[lk + 0][lm] = b0.x; Bs[lk + 1][lm] = b0.y; Bs[lk + 2][lm] = b0.z; Bs[lk + 3][lm] = b0.w;
        Bs[lk + 4][lm] = b1.x; Bs[lk + 5][lm] = b1.y; Bs[lk + 6][lm] = b1.z; Bs[lk + 7][lm] = b1.w;
        __syncthreads();
#pragma unroll
        for (int k = 0; k < 16; k++) {
            ull a2[4];
#pragma unroll
            for (int i = 0; i < 4; i++) a2[i] = *(const ull*)&As[k][tm + 2 * i];
            float4 w0 = *(const float4*)&Bs[k][tn];
            float4 w1 = *(const float4*)&Bs[k][tn + 4];
            ull b2[8];
            b2[0] = pack2f(w0.x, w0.x); b2[1] = pack2f(w0.y, w0.y);
            b2[2] = pack2f(w0.z, w0.z); b2[3] = pack2f(w0.w, w0.w);
            b2[4] = pack2f(w1.x, w1.x); b2[5] = pack2f(w1.y, w1.y);
            b2[6] = pack2f(w1.z, w1.z); b2[7] = pack2f(w1.w, w1.w);
#pragma unroll
            for (int i = 0; i < 4; i++)
#pragma unroll
                for (int j = 0; j < 8; j++) acc[i][j] = fma2(a2[i], b2[j], acc[i][j]);
        }
    }
#pragma unroll
    for (int i = 0; i < 4; i++) {
        float r0[8], r1[8];
#pragma unroll
        for (int j = 0; j < 8; j++) {
            float2 p = unpack2(acc[i][j]);
            r0[j] = p.x + bias[j];
            r1[j] = p.y + bias[j];
        }
        float* p0 = d_gx + ((size_t)dir * 65536 + (m0 + tm + 2 * i)) * 1024 + nloc0 + tn;
        float* p1 = p0 + 1024;
        *(float4*)(p0)     = make_float4(r0[0], r0[1], r0[2], r0[3]);
        *(float4*)(p0 + 4) = make_float4(r0[4], r0[5], r0[6], r0[7]);
        *(float4*)(p1)     = make_float4(r1[0], r1[1], r1[2], r1[3]);
        *(float4*)(p1 + 4) = make_float4(r1[4], r1[5], r1[6], r1[7]);
    }
}

// ---------------- K2: LSTM recurrence (512 threads, pipelined) ----------------
__device__ __forceinline__ void mv_stage(uint4 a0, uint4 a1, const float* hbase, int ch,
                                         ull acc0[4], ull acc1[4]) {
    ull wa[4], wb[4];
    wa[0] = bf2f2(a0.x); wa[1] = bf2f2(a0.y); wa[2] = bf2f2(a0.z); wa[3] = bf2f2(a0.w);
    wb[0] = bf2f2(a1.x); wb[1] = bf2f2(a1.y); wb[2] = bf2f2(a1.z); wb[3] = bf2f2(a1.w);
#pragma unroll
    for (int b = 0; b < 4; b++) {
        const ulonglong2* hp = (const ulonglong2*)(hbase + b * 256 + ch * 8);
        ulonglong2 q0 = hp[0];
        ulonglong2 q1 = hp[1];
        acc0[b] = fma2(wa[0], q0.x, acc0[b]); acc0[b] = fma2(wa[1], q0.y, acc0[b]);
        acc0[b] = fma2(wa[2], q1.x, acc0[b]); acc0[b] = fma2(wa[3], q1.y, acc0[b]);
        acc1[b] = fma2(wb[0], q0.x, acc1[b]); acc1[b] = fma2(wb[1], q0.y, acc1[b]);
        acc1[b] = fma2(wb[2], q1.x, acc1[b]); acc1[b] = fma2(wb[3], q1.y, acc1[b]);
    }
}

__global__ void __launch_bounds__(512, 1) k_recur() {
    int tid = threadIdx.x;                 // 0..511
    int dir = blockIdx.x >> 5;
    int b0 = (blockIdx.x & 31) * 4;
    int j = tid & 255;
    int upper = tid >> 8;                  // 0: gates i,g ; 1: gates f,o
    int r0 = upper ? 256 + j : j;          // f_j : i_j
    int r1 = upper ? 768 + j : 512 + j;    // o_j : g_j

    const __nv_bfloat16* WT = d_whh + (size_t)dir * 32 * 1024 * 8;
    const uint4* w0 = (const uint4*)(WT + (size_t)r0 * 8);   // stride per ch = 1024 uint4
    const uint4* w1 = (const uint4*)(WT + (size_t)r1 * 8);

    __shared__ __align__(16) float shh[2][4][256];
    __shared__ __align__(16) float pre[4][4][256];

    for (int i = tid; i < 4 * 256; i += 512) ((float*)shh)[i] = 0.f;   // zero shh[0]
    float cc0 = 0.f, cc1 = 0.f;            // cell state for batches (2*upper, 2*upper+1)
    __syncthreads();

    const float* gxbase = d_gx + (size_t)dir * 65536 * 1024;
    int buf = 0;

    for (int step = 0; step < 512; step++) {
        int l = dir ? (511 - step) : step;
        const float* gxp = gxbase + (size_t)(l * 128 + b0) * 1024;
        float gx0[4], gx1[4];
#pragma unroll
        for (int b = 0; b < 4; b++) {
            gx0[b] = __ldg(gxp + b * 1024 + r0);
            gx1[b] = __ldg(gxp + b * 1024 + r1);
        }

        ull acc0[4] = {0, 0, 0, 0}, acc1[4] = {0, 0, 0, 0};
        const float* hb = &shh[buf][0][0];

        uint4 c00 = w0[0],    c01 = w1[0];
        uint4 c10 = w0[1024], c11 = w1[1024];
#pragma unroll 4
        for (int ch = 0; ch < 32; ch += 2) {
            uint4 n00, n01, n10, n11;
            if (ch + 2 < 32) {
                n00 = w0[(ch + 2) * 1024]; n01 = w1[(ch + 2) * 1024];
                n10 = w0[(ch + 3) * 1024]; n11 = w1[(ch + 3) * 1024];
            }
            mv_stage(c00, c01, hb, ch,     acc0, acc1);
            mv_stage(c10, c11, hb, ch + 1, acc0, acc1);
            c00 = n00; c01 = n01; c10 = n10; c11 = n11;
        }

        // reduce k-pairs, add input preacts, publish gate preacts
        int g0 = upper ? 1 : 0, g1 = upper ? 3 : 2;
#pragma unroll
        for (int b = 0; b < 4; b++) {
            float2 u0 = unpack2(acc0[b]);
            float2 u1 = unpack2(acc1[b]);
            pre[b][g0][j] = u0.x + u0.y + gx0[b];
            pre[b][g1][j] = u1.x + u1.y + gx1[b];
        }
        __syncthreads();

        // cell update: each thread handles 2 batch rows for dim j
        int bb = upper * 2;
#pragma unroll
        for (int q = 0; q < 2; q++) {
            int b = bb + q;
            float pi = pre[b][0][j], pf = pre[b][1][j];
            float pg = pre[b][2][j], po = pre[b][3][j];
            float i_ = sigf(pi), f_ = sigf(pf), g_ = tanhx(pg), o_ = sigf(po);
            float c = q ? cc1 : cc0;
            c = f_ * c + i_ * g_;
            if (q) cc1 = c; else cc0 = c;
            float hv = o_ * tanhx(c);
            shh[buf ^ 1][b][j] = hv;
            d_hcat[((size_t)(b0 + b) * 512 + l) * 512 + dir * 256 + j] = hv;
        }
        buf ^= 1;
        __syncthreads();
    }
}

// ---------------- K3: emission = hcat @ w_cls^T + b_cls ----------------
__global__ void __launch_bounds__(256) k_emis(const float* __restrict__ wcls,
                                              const float* __restrict__ bcls) {
    __shared__ float wc[16 * 512];
    int tid = threadIdx.x;
    for (int i = tid; i < 16 * 512 / 4; i += 256)
        ((float4*)wc)[i] = ((const float4*)wcls)[i];
    __syncthreads();
    int m = blockIdx.x * 8 + (tid >> 5);
    int lane = tid & 31;
    float acc[16];
#pragma unroll
    for (int t = 0; t < 16; t++) acc[t] = 0.f;
    const float* hp = d_hcat + (size_t)m * 512;
#pragma unroll
    for (int it = 0; it < 4; it++) {
        int k = it * 128 + lane * 4;
        float4 h4 = *(const float4*)(hp + k);
#pragma unroll
        for (int t = 0; t < 16; t++) {
            float4 w4 = *(const float4*)(wc + t * 512 + k);
            acc[t] += h4.x * w4.x + h4.y * w4.y + h4.z * w4.z + h4.w * w4.w;
        }
    }
#pragma unroll
    for (int t = 0; t < 16; t++)
#pragma unroll
        for (int off = 16; off; off >>= 1) acc[t] += __shfl_xor_sync(0xffffffffu, acc[t], off);
    if (lane < 16) {
        float v = acc[0];
#pragma unroll
        for (int t = 1; t < 16; t++) v = (lane == t) ? acc[t] : v;
        d_emission[(size_t)m * 16 + lane] = v + bcls[lane];
    }
}

// ---------------- K4: CRF golden + forward (1 warp / batch row) ----------------
__global__ void k_crf(const int* __restrict__ tag, const float* __restrict__ trans) {
    __shared__ float tr[256];
    int b = blockIdx.x, lane = threadIdx.x;
    for (int i = lane; i < 256; i += 32) tr[i] = trans[i];
    __syncwarp();
    int cur = lane & 15;
    float tcol[16];
#pragma unroll
    for (int p = 0; p < 16; p++) tcol[p] = tr[p * 16 + cur];
    const int* tg = tag + b * 512;
    int len = 0;
    for (int l2 = lane; l2 < 512; l2 += 32) len += (tg[l2] != 0);
#pragma unroll
    for (int off = 16; off; off >>= 1) len += __shfl_xor_sync(0xffffffffu, len, off);

    const float* em = d_emission + (size_t)b * 512 * 16;
    float gsum = 0.f;
    for (int l2 = lane; l2 < 512; l2 += 32)
        if (l2 < len) {
            int t = tg[l2];
            int pv = l2 ? tg[l2 - 1] : 14;       // START=14
            gsum += em[l2 * 16 + t] + tr[pv * 16 + t];
        }
#pragma unroll
    for (int off = 16; off; off >>= 1) gsum += __shfl_xor_sync(0xffffffffu, gsum, off);

    float score = em[cur] + tr[14 * 16 + cur];
    for (int t = 1; t < 512; t++) {
        float m = -1e30f, s = 0.f;
#pragma unroll
        for (int p = 0; p < 16; p++) {
            float v = __shfl_sync(0xffffffffu, score, p) + tcol[p];
            float mn = fmaxf(m, v);
            s = s * __expf(m - mn) + __expf(v - mn);
            m = mn;
        }
        float ns = em[t * 16 + cur] + m + __logf(s);
        score = (t < len) ? ns : score;
    }
    if (lane == 15) atomicAdd(&d_acc[0], (double)score);  // END=15
    if (lane == 0)  atomicAdd(&d_acc[1], (double)gsum);
}

__global__ void k_final(float* out) {
    out[0] = (float)((d_acc[0] - d_acc[1]) / 128.0);
}

// ---------------- launch ----------------
extern "C" void kernel_launch(void* const* d_in, const int* in_sizes, int n_in,
                              void* d_out, int out_size) {
    const int*   batch_data = (const int*)d_in[0];
    const int*   batch_tag  = (const int*)d_in[1];
    const float* emb        = (const float*)d_in[2];
    const float* w_ih_f     = (const float*)d_in[3];
    const float* w_hh_f     = (const float*)d_in[4];
    const float* b_f        = (const float*)d_in[5];
    const float* w_ih_b     = (const float*)d_in[6];
    const float* w_hh_b     = (const float*)d_in[7];
    const float* b_b        = (const float*)d_in[8];
    const float* w_cls      = (const float*)d_in[9];
    const float* b_cls      = (const float*)d_in[10];
    const float* transition = (const float*)d_in[11];

    k_prep<<<2048, 256>>>(w_hh_f, w_hh_b);
    k_gather<<<8192, 256>>>(batch_data, emb);
    k_gemm<<<dim3(512, 16), 256>>>(w_ih_f, w_ih_b, b_f, b_b);
    k_recur<<<64, 512>>>();
    k_emis<<<8192, 256>>>(w_cls, b_cls);
    k_crf<<<128, 32>>>(batch_tag, transition);
    k_final<<<1, 1>>>((float*)d_out);
}

// round 4
// speedup vs baseline: 2.4467x; 1.3959x over previous
#include <cuda_runtime.h>
#include <cuda_bf16.h>

typedef unsigned long long ull;

// ---------------- device scratch (no runtime allocation) ----------------
__device__ float d_x[(size_t)65536 * 256];            // gathered embeddings [m][256], m = l*128+b
__device__ float d_gx[(size_t)2 * 65536 * 1024];      // input gate preacts [dir][m][1024]
__device__ float d_hcat[(size_t)128 * 512 * 512];     // [b][l][hf|hb]
__device__ float d_emission[(size_t)65536 * 16];      // [b*512+l][16]
__device__ __nv_bfloat16 d_whh[2 * 32 * 1024 * 8];    // bf16 W_hh transposed: [dir][ch][row][8]
__device__ double d_acc[2];                           // [all_path, golden]

// ---------------- f32x2 helpers ----------------
__device__ __forceinline__ ull fma2(ull a, ull b, ull c) {
    ull d; asm("fma.rn.f32x2 %0,%1,%2,%3;" : "=l"(d) : "l"(a), "l"(b), "l"(c)); return d;
}
__device__ __forceinline__ ull pack2f(float x, float y) {
    ull r; asm("mov.b64 %0,{%1,%2};" : "=l"(r) : "f"(x), "f"(y)); return r;
}
__device__ __forceinline__ float2 unpack2(ull v) {
    float x, y; asm("mov.b64 {%0,%1},%2;" : "=f"(x), "=f"(y) : "l"(v));
    float2 r; r.x = x; r.y = y; return r;
}
// one u32 holding 2 bf16 -> packed f32x2
__device__ __forceinline__ ull bf2f2(unsigned w) {
    unsigned lo = w << 16, hi = w & 0xffff0000u;
    ull r; asm("mov.b64 %0,{%1,%2};" : "=l"(r) : "r"(lo), "r"(hi)); return r;
}
__device__ __forceinline__ float bflo(unsigned w) { return __uint_as_float(w << 16); }
__device__ __forceinline__ float bfhi(unsigned w) { return __uint_as_float(w & 0xffff0000u); }
__device__ __forceinline__ float sigf(float x) { return 1.f / (1.f + __expf(-x)); }
__device__ __forceinline__ float tanhx(float x) { return 2.f / (1.f + __expf(-2.f * x)) - 1.f; }

__device__ __forceinline__ unsigned smem_u32(const void* p) {
    unsigned a;
    asm("{ .reg .u64 t; cvta.to.shared.u64 t, %1; cvt.u32.u64 %0, t; }" : "=r"(a) : "l"(p));
    return a;
}
__device__ __forceinline__ unsigned mapa_u32(unsigned a, unsigned rank) {
    unsigned d; asm("mapa.shared::cluster.u32 %0,%1,%2;" : "=r"(d) : "r"(a), "r"(rank));
    return d;
}

// ---------------- K0: prep (bf16 transposed weights, zero accumulators) ----------------
__global__ void k_prep(const float* __restrict__ whf, const float* __restrict__ whb) {
    int e = blockIdx.x * 256 + threadIdx.x;   // 0..524287
    int dir = e >> 18;
    int rem = e & 262143;
    int row = rem >> 8, k = rem & 255;
    const float* src = dir ? whb : whf;
    int ch = k >> 3, jj = k & 7;
    d_whh[((size_t)(dir * 32 + ch) * 1024 + row) * 8 + jj] = __float2bfloat16(src[row * 256 + k]);
    if (e < 2) d_acc[e] = 0.0;
}

// ---------------- K1a: embedding gather ----------------
__global__ void k_gather(const int* __restrict__ bd, const float* __restrict__ emb) {
    int m = blockIdx.x * 8 + (threadIdx.x >> 5);
    int lane = threadIdx.x & 31;
    int b = m & 127, l = m >> 7;
    int idx = bd[b * 512 + l];
    const float4* src = (const float4*)(emb + (size_t)idx * 256);
    float4* dst = (float4*)(d_x + (size_t)m * 256);
    dst[lane] = src[lane];
    dst[lane + 32] = src[lane + 32];
}

// ---------------- K1b: input projection SGEMM (f32x2) ----------------
__global__ void __launch_bounds__(256) k_gemm(const float* __restrict__ wf,
                                              const float* __restrict__ wb,
                                              const float* __restrict__ bf,
                                              const float* __restrict__ bb) {
    __shared__ float As[16][128];
    __shared__ float Bs[16][128];
    int tid = threadIdx.x;
    int m0 = blockIdx.x * 128;
    int n0 = blockIdx.y * 128;
    int dir = n0 >> 10;
    int nloc0 = n0 & 1023;
    const float* W  = dir ? wb : wf;
    const float* Bv = dir ? bb : bf;

    int lm = tid >> 1;
    int lk = (tid & 1) * 8;
    int tm = (tid & 15) * 8;
    int tn = (tid >> 4) * 8;

    float bias[8];
#pragma unroll
    for (int j = 0; j < 8; j++) bias[j] = Bv[nloc0 + tn + j];

    ull acc[4][8];
#pragma unroll
    for (int i = 0; i < 4; i++)
#pragma unroll
        for (int j = 0; j < 8; j++) acc[i][j] = 0ull;

    for (int k0 = 0; k0 < 256; k0 += 16) {
        float4 a0 = *(const float4*)(d_x + (size_t)(m0 + lm) * 256 + k0 + lk);
        float4 a1 = *(const float4*)(d_x + (size_t)(m0 + lm) * 256 + k0 + lk + 4);
        float4 b0 = *(const float4*)(W + (size_t)(nloc0 + lm) * 256 + k0 + lk);
        float4 b1 = *(const float4*)(W + (size_t)(nloc0 + lm) * 256 + k0 + lk + 4);
        __syncthreads();
        As[lk + 0][lm] = a0.x; As[lk + 1][lm] = a0.y; As[lk + 2][lm] = a0.z; As[lk + 3][lm] = a0.w;
        As[lk + 4][lm] = a1.x; As[lk + 5][lm] = a1.y; As[lk + 6][lm] = a1.z; As[lk + 7][lm] = a1.w;
        Bs[lk + 0][lm] = b0.x; Bs[lk + 1][lm] = b0.y; Bs[lk + 2][lm] = b0.z; Bs[lk + 3][lm] = b0.w;
        Bs[lk + 4][lm] = b1.x; Bs[lk + 5][lm] = b1.y; Bs[lk + 6][lm] = b1.z; Bs[lk + 7][lm] = b1.w;
        __syncthreads();
#pragma unroll
        for (int k = 0; k < 16; k++) {
            ull a2[4];
#pragma unroll
            for (int i = 0; i < 4; i++) a2[i] = *(const ull*)&As[k][tm + 2 * i];
            float4 w0 = *(const float4*)&Bs[k][tn];
            float4 w1 = *(const float4*)&Bs[k][tn + 4];
            ull b2[8];
            b2[0] = pack2f(w0.x, w0.x); b2[1] = pack2f(w0.y, w0.y);
            b2[2] = pack2f(w0.z, w0.z); b2[3] = pack2f(w0.w, w0.w);
            b2[4] = pack2f(w1.x, w1.x); b2[5] = pack2f(w1.y, w1.y);
            b2[6] = pack2f(w1.z, w1.z); b2[7] = pack2f(w1.w, w1.w);
#pragma unroll
            for (int i = 0; i < 4; i++)
#pragma unroll
                for (int j = 0; j < 8; j++) acc[i][j] = fma2(a2[i], b2[j], acc[i][j]);
        }
    }
#pragma unroll
    for (int i = 0; i < 4; i++) {
        float r0[8], r1[8];
#pragma unroll
        for (int j = 0; j < 8; j++) {
            float2 p = unpack2(acc[i][j]);
            r0[j] = p.x + bias[j];
            r1[j] = p.y + bias[j];
        }
        float* p0 = d_gx + ((size_t)dir * 65536 + (m0 + tm + 2 * i)) * 1024 + nloc0 + tn;
        float* p1 = p0 + 1024;
        *(float4*)(p0)     = make_float4(r0[0], r0[1], r0[2], r0[3]);
        *(float4*)(p0 + 4) = make_float4(r0[4], r0[5], r0[6], r0[7]);
        *(float4*)(p1)     = make_float4(r1[0], r1[1], r1[2], r1[3]);
        *(float4*)(p1 + 4) = make_float4(r1[4], r1[5], r1[6], r1[7]);
    }
}

// ---------------- K2: LSTM recurrence, cluster-of-2 k-split ----------------
__device__ __forceinline__ void mv_stage(uint4 a0, uint4 a1, const float* hbase, int ch,
                                         ull acc0[4], ull acc1[4]) {
    ull wa[4], wb[4];
    wa[0] = bf2f2(a0.x); wa[1] = bf2f2(a0.y); wa[2] = bf2f2(a0.z); wa[3] = bf2f2(a0.w);
    wb[0] = bf2f2(a1.x); wb[1] = bf2f2(a1.y); wb[2] = bf2f2(a1.z); wb[3] = bf2f2(a1.w);
#pragma unroll
    for (int b = 0; b < 4; b++) {
        const ulonglong2* hp = (const ulonglong2*)(hbase + b * 256 + ch * 8);
        ulonglong2 q0 = hp[0];
        ulonglong2 q1 = hp[1];
        acc0[b] = fma2(wa[0], q0.x, acc0[b]); acc0[b] = fma2(wa[1], q0.y, acc0[b]);
        acc0[b] = fma2(wa[2], q1.x, acc0[b]); acc0[b] = fma2(wa[3], q1.y, acc0[b]);
        acc1[b] = fma2(wb[0], q0.x, acc1[b]); acc1[b] = fma2(wb[1], q0.y, acc1[b]);
        acc1[b] = fma2(wb[2], q1.x, acc1[b]); acc1[b] = fma2(wb[3], q1.y, acc1[b]);
    }
}

__global__ void __launch_bounds__(512, 1) __cluster_dims__(2, 1, 1) k_recur() {
    int tid = threadIdx.x;                 // 0..511
    unsigned rank;
    asm("mov.u32 %0, %%cluster_ctarank;" : "=r"(rank));
    int cid = blockIdx.x >> 1;
    int dir = cid >> 5;
    int b0 = (cid & 31) * 4;
    int j = tid & 255;
    int upper = tid >> 8;                  // 0: gates i(0),g(2) ; 1: gates f(1),o(3)
    int r0 = upper ? 256 + j : j;
    int r1 = upper ? 768 + j : 512 + j;
    int g0 = upper ? 1 : 0, g1 = upper ? 3 : 2;

    // weight slice for this rank's k-half: chunks [rank*16, rank*16+16)
    const uint4* wbase = (const uint4*)(d_whh + (size_t)dir * 32 * 1024 * 8) + (size_t)rank * 16 * 1024;
    const uint4* w0 = wbase + r0;          // index by ch*1024
    const uint4* w1 = wbase + r1;

    __shared__ __align__(16) float shh[2][4][256];       // full h, double buffered (8 KB)
    __shared__ __align__(16) float pre[4][4][256];       // local partials (+gx for owned b) (16 KB)
    __shared__ __align__(16) unsigned pre2[2][4][2][256];// peer partials bf16x2, dbl-buf (16 KB)
    __shared__ __align__(8) ull mbar[2];

    for (int i = tid; i < 4 * 256; i += 512) ((float*)shh)[i] = 0.f;  // zero shh[0]
    if (tid == 0) {
        unsigned m0a = smem_u32(&mbar[0]);
        unsigned m1a = smem_u32(&mbar[1]);
        asm volatile("mbarrier.init.shared.b64 [%0], 1;" :: "r"(m0a) : "memory");
        asm volatile("mbarrier.init.shared.b64 [%0], 1;" :: "r"(m1a) : "memory");
    }
    __syncthreads();
    asm volatile("barrier.cluster.arrive.aligned;" ::: "memory");
    asm volatile("barrier.cluster.wait.aligned;" ::: "memory");

    unsigned peer = rank ^ 1u;
    unsigned peer_mbar0 = mapa_u32(smem_u32(&mbar[0]), peer);
    unsigned peer_mbar1 = mapa_u32(smem_u32(&mbar[1]), peer);
    unsigned peer_pre2  = mapa_u32(smem_u32(&pre2[0][0][0][0]), peer);
    unsigned my_mbar0   = smem_u32(&mbar[0]);
    unsigned my_mbar1   = smem_u32(&mbar[1]);

    float cc0 = 0.f, cc1 = 0.f;            // cell states for (b = upper*2, upper*2+1)
    const float* gxbase = d_gx + (size_t)dir * 65536 * 1024;
    int buf = 0;
    int bown = (int)rank * 2;              // this rank owns gx for batches bown, bown+1

    for (int step = 0; step < 512; step++) {
        int l = dir ? (511 - step) : step;
        float gx0[2], gx1[2];
#pragma unroll
        for (int q = 0; q < 2; q++) {
            const float* gxp = gxbase + (size_t)(l * 128 + b0 + bown + q) * 1024;
            gx0[q] = __ldg(gxp + r0);
            gx1[q] = __ldg(gxp + r1);
        }

        ull acc0[4] = {0, 0, 0, 0}, acc1[4] = {0, 0, 0, 0};
        const float* hb = &shh[buf][0][0] + (int)rank * 128;

        uint4 c00 = w0[0],    c01 = w1[0];
        uint4 c10 = w0[1024], c11 = w1[1024];
#pragma unroll 4
        for (int ch = 0; ch < 16; ch += 2) {
            uint4 n00, n01, n10, n11;
            if (ch + 2 < 16) {
                n00 = w0[(ch + 2) * 1024]; n01 = w1[(ch + 2) * 1024];
                n10 = w0[(ch + 3) * 1024]; n11 = w1[(ch + 3) * 1024];
            }
            mv_stage(c00, c01, hb, ch,     acc0, acc1);
            mv_stage(c10, c11, hb, ch + 1, acc0, acc1);
            c00 = n00; c01 = n01; c10 = n10; c11 = n11;
        }

        // publish partials: local fp32, peer bf16x2 via DSMEM
#pragma unroll
        for (int b = 0; b < 4; b++) {
            float2 u0 = unpack2(acc0[b]);
            float2 u1 = unpack2(acc1[b]);
            float s0 = u0.x + u0.y;
            float s1 = u1.x + u1.y;
            if ((b >> 1) == (int)rank) { s0 += gx0[b & 1]; s1 += gx1[b & 1]; }
            pre[b][g0][j] = s0;
            pre[b][g1][j] = s1;
            unsigned pk;
            asm("cvt.rn.bf16x2.f32 %0,%1,%2;" : "=r"(pk) : "f"(s1), "f"(s0));
            unsigned addr = peer_pre2 + ((((unsigned)buf * 4 + b) * 2 + upper) * 256 + j) * 4;
            asm volatile("st.shared::cluster.u32 [%0],%1;" :: "r"(addr), "r"(pk) : "memory");
        }
        __syncthreads();                     // local pre ready; all remote stores issued
        if (tid == 0) {
            unsigned pm = (step & 1) ? peer_mbar1 : peer_mbar0;
            asm volatile("mbarrier.arrive.release.cluster.shared::cluster.b64 _, [%0];"
                         :: "r"(pm) : "memory");
        }
        {
            unsigned mm = (step & 1) ? my_mbar1 : my_mbar0;
            unsigned ph = (unsigned)(step >> 1) & 1u;
            unsigned done;
            asm volatile("{\n\t.reg .pred p;\n\t"
                         "mbarrier.try_wait.parity.acquire.cluster.shared::cta.b64 p, [%1], %2;\n\t"
                         "selp.b32 %0, 1, 0, p;\n\t}"
                         : "=r"(done) : "r"(mm), "r"(ph) : "memory");
            while (!done) {
                asm volatile("{\n\t.reg .pred p;\n\t"
                             "mbarrier.try_wait.parity.acquire.cluster.shared::cta.b64 p, [%1], %2, 0x989680;\n\t"
                             "selp.b32 %0, 1, 0, p;\n\t}"
                             : "=r"(done) : "r"(mm), "r"(ph) : "memory");
            }
        }

        // cell update (redundant across the pair -> local full h, no h exchange)
#pragma unroll
        for (int q = 0; q < 2; q++) {
            int b = upper * 2 + q;
            unsigned v0 = pre2[buf][b][0][j];   // lo: gate i(0), hi: gate g(2)
            unsigned v1 = pre2[buf][b][1][j];   // lo: gate f(1), hi: gate o(3)
            float pi = pre[b][0][j] + bflo(v0);
            float pf = pre[b][1][j] + bflo(v1);
            float pg = pre[b][2][j] + bfhi(v0);
            float po = pre[b][3][j] + bfhi(v1);
            float i_ = sigf(pi), f_ = sigf(pf), g_ = tanhx(pg), o_ = sigf(po);
            float c = q ? cc1 : cc0;
            c = f_ * c + i_ * g_;
            if (q) cc1 = c; else cc0 = c;
            float hv = o_ * tanhx(c);
            shh[buf ^ 1][b][j] = hv;
            if (upper == (int)rank)             // each hcat element written once per cluster
                d_hcat[((size_t)(b0 + b) * 512 + l) * 512 + dir * 256 + j] = hv;
        }
        buf ^= 1;
        __syncthreads();
    }

    asm volatile("barrier.cluster.arrive.aligned;" ::: "memory");
    asm volatile("barrier.cluster.wait.aligned;" ::: "memory");
}

// ---------------- K3: emission = hcat @ w_cls^T + b_cls ----------------
__global__ void __launch_bounds__(256) k_emis(const float* __restrict__ wcls,
                                              const float* __restrict__ bcls) {
    __shared__ float wc[16 * 512];
    int tid = threadIdx.x;
    for (int i = tid; i < 16 * 512 / 4; i += 256)
        ((float4*)wc)[i] = ((const float4*)wcls)[i];
    __syncthreads();
    int m = blockIdx.x * 8 + (tid >> 5);
    int lane = tid & 31;
    float acc[16];
#pragma unroll
    for (int t = 0; t < 16; t++) acc[t] = 0.f;
    const float* hp = d_hcat + (size_t)m * 512;
#pragma unroll
    for (int it = 0; it < 4; it++) {
        int k = it * 128 + lane * 4;
        float4 h4 = *(const float4*)(hp + k);
#pragma unroll
        for (int t = 0; t < 16; t++) {
            float4 w4 = *(const float4*)(wc + t * 512 + k);
            acc[t] += h4.x * w4.x + h4.y * w4.y + h4.z * w4.z + h4.w * w4.w;
        }
    }
#pragma unroll
    for (int t = 0; t < 16; t++)
#pragma unroll
        for (int off = 16; off; off >>= 1) acc[t] += __shfl_xor_sync(0xffffffffu, acc[t], off);
    if (lane < 16) {
        float v = acc[0];
#pragma unroll
        for (int t = 1; t < 16; t++) v = (lane == t) ? acc[t] : v;
        d_emission[(size_t)m * 16 + lane] = v + bcls[lane];
    }
}

// ---------------- K4: CRF golden + forward (1 warp / batch row) ----------------
__global__ void k_crf(const int* __restrict__ tag, const float* __restrict__ trans) {
    __shared__ float tr[256];
    int b = blockIdx.x, lane = threadIdx.x;
    for (int i = lane; i < 256; i += 32) tr[i] = trans[i];
    __syncwarp();
    int cur = lane & 15;
    float tcol[16];
#pragma unroll
    for (int p = 0; p < 16; p++) tcol[p] = tr[p * 16 + cur];
    const int* tg = tag + b * 512;
    int len = 0;
    for (int l2 = lane; l2 < 512; l2 += 32) len += (tg[l2] != 0);
#pragma unroll
    for (int off = 16; off; off >>= 1) len += __shfl_xor_sync(0xffffffffu, len, off);

    const float* em = d_emission + (size_t)b * 512 * 16;
    float gsum = 0.f;
    for (int l2 = lane; l2 < 512; l2 += 32)
        if (l2 < len) {
            int t = tg[l2];
            int pv = l2 ? tg[l2 - 1] : 14;       // START=14
            gsum += em[l2 * 16 + t] + tr[pv * 16 + t];
        }
#pragma unroll
    for (int off = 16; off; off >>= 1) gsum += __shfl_xor_sync(0xffffffffu, gsum, off);

    float score = em[cur] + tr[14 * 16 + cur];
    for (int t = 1; t < 512; t++) {
        float m = -1e30f, s = 0.f;
#pragma unroll
        for (int p = 0; p < 16; p++) {
            float v = __shfl_sync(0xffffffffu, score, p) + tcol[p];
            float mn = fmaxf(m, v);
            s = s * __expf(m - mn) + __expf(v - mn);
            m = mn;
        }
        float ns = em[t * 16 + cur] + m + __logf(s);
        score = (t < len) ? ns : score;
    }
    if (lane == 15) atomicAdd(&d_acc[0], (double)score);  // END=15
    if (lane == 0)  atomicAdd(&d_acc[1], (double)gsum);
}

__global__ void k_final(float* out) {
    out[0] = (float)((d_acc[0] - d_acc[1]) / 128.0);
}

// ---------------- launch ----------------
extern "C" void kernel_launch(void* const* d_in, const int* in_sizes, int n_in,
                              void* d_out, int out_size) {
    const int*   batch_data = (const int*)d_in[0];
    const int*   batch_tag  = (const int*)d_in[1];
    const float* emb        = (const float*)d_in[2];
    const float* w_ih_f     = (const float*)d_in[3];
    const float* w_hh_f     = (const float*)d_in[4];
    const float* b_f        = (const float*)d_in[5];
    const float* w_ih_b     = (const float*)d_in[6];
    const float* w_hh_b     = (const float*)d_in[7];
    const float* b_b        = (const float*)d_in[8];
    const float* w_cls      = (const float*)d_in[9];
    const float* b_cls      = (const float*)d_in[10];
    const float* transition = (const float*)d_in[11];

    k_prep<<<2048, 256>>>(w_hh_f, w_hh_b);
    k_gather<<<8192, 256>>>(batch_data, emb);
    k_gemm<<<dim3(512, 16), 256>>>(w_ih_f, w_ih_b, b_f, b_b);
    k_recur<<<128, 512>>>();
    k_emis<<<8192, 256>>>(w_cls, b_cls);
    k_crf<<<128, 32>>>(batch_tag, transition);
    k_final<<<1, 1>>>((float*)d_out);
}

// round 5
// speedup vs baseline: 2.7122x; 1.1085x over previous
#include <cuda_runtime.h>
#include <cuda_bf16.h>

typedef unsigned long long ull;

// ---------------- device scratch (no runtime allocation) ----------------
__device__ float d_x[(size_t)65536 * 256];            // gathered embeddings [m][256], m = l*128+b
__device__ float d_gx[(size_t)2 * 65536 * 1024];      // input gate preacts [dir][m][1024]
__device__ float d_hcat[(size_t)128 * 512 * 512];     // [b][l][hf|hb]
__device__ float d_emission[(size_t)65536 * 16];      // [b*512+l][16]
__device__ uint4 d_whh2[65536];                       // W_hh pre-swizzled into mma B fragments (1MB)
__device__ double d_acc[2];                           // [all_path, golden]

// ---------------- f32x2 helpers (used by k_gemm) ----------------
__device__ __forceinline__ ull fma2(ull a, ull b, ull c) {
    ull d; asm("fma.rn.f32x2 %0,%1,%2,%3;" : "=l"(d) : "l"(a), "l"(b), "l"(c)); return d;
}
__device__ __forceinline__ ull pack2f(float x, float y) {
    ull r; asm("mov.b64 %0,{%1,%2};" : "=l"(r) : "f"(x), "f"(y)); return r;
}
__device__ __forceinline__ float2 unpack2(ull v) {
    float x, y; asm("mov.b64 {%0,%1},%2;" : "=f"(x), "=f"(y) : "l"(v));
    float2 r; r.x = x; r.y = y; return r;
}
__device__ __forceinline__ float bfhalf(unsigned u, int hi) {
    return __uint_as_float(hi ? (u & 0xffff0000u) : (u << 16));
}
__device__ __forceinline__ float sigf(float x) { return 1.f / (1.f + __expf(-x)); }
__device__ __forceinline__ float tanhx(float x) { return 2.f / (1.f + __expf(-2.f * x)) - 1.f; }

__device__ __forceinline__ unsigned smem_u32(const void* p) {
    unsigned a;
    asm("{ .reg .u64 t; cvta.to.shared.u64 t, %1; cvt.u32.u64 %0, t; }" : "=r"(a) : "l"(p));
    return a;
}
__device__ __forceinline__ unsigned mapa_u32(unsigned a, unsigned rank) {
    unsigned d; asm("mapa.shared::cluster.u32 %0,%1,%2;" : "=r"(d) : "r"(a), "r"(rank));
    return d;
}

// mma + ldmatrix macros
#define MMA_BF16(C, A, B0, B1)                                                          \
    asm volatile("mma.sync.aligned.m16n8k16.row.col.f32.bf16.bf16.f32 "                 \
                 "{%0,%1,%2,%3},{%4,%5,%6,%7},{%8,%9},{%0,%1,%2,%3};"                   \
                 : "+f"((C)[0]), "+f"((C)[1]), "+f"((C)[2]), "+f"((C)[3])               \
                 : "r"((A)[0]), "r"((A)[1]), "r"((A)[2]), "r"((A)[3]),                  \
                   "r"(B0), "r"(B1))
#define LDSM4(R, ADDR)                                                                  \
    asm volatile("ldmatrix.sync.aligned.m8n8.x4.shared.b16 {%0,%1,%2,%3},[%4];"         \
                 : "=r"((R)[0]), "=r"((R)[1]), "=r"((R)[2]), "=r"((R)[3]) : "r"(ADDR))

// ---------------- K0: prep (weights -> mma B-fragment layout, zero acc) ----------------
__device__ __forceinline__ unsigned pkbf(const float* s, int n, int k) {
    unsigned short lo = __bfloat16_as_ushort(__float2bfloat16(s[n * 256 + k]));
    unsigned short hi = __bfloat16_as_ushort(__float2bfloat16(s[n * 256 + k + 1]));
    return ((unsigned)hi << 16) | (unsigned)lo;
}
__global__ void k_prep(const float* __restrict__ whf, const float* __restrict__ whb) {
    int e = blockIdx.x * 256 + threadIdx.x;   // 65536
    int lane = e & 31, p = (e >> 5) & 3, kt = (e >> 7) & 7, w = (e >> 10) & 15;
    int rank = (e >> 14) & 1, dir = (e >> 15) & 1;
    const float* src = dir ? whb : whf;
    int n0 = w * 64 + p * 16 + (lane >> 2);   // gate row for nt=2p; nt=2p+1 -> n0+8
    int k0 = rank * 128 + kt * 16 + (lane & 3) * 2;
    uint4 v;
    v.x = pkbf(src, n0, k0);
    v.y = pkbf(src, n0, k0 + 8);
    v.z = pkbf(src, n0 + 8, k0);
    v.w = pkbf(src, n0 + 8, k0 + 8);
    d_whh2[e] = v;
    if (e < 2) d_acc[e] = 0.0;
}

// ---------------- K1a: embedding gather ----------------
__global__ void k_gather(const int* __restrict__ bd, const float* __restrict__ emb) {
    int m = blockIdx.x * 8 + (threadIdx.x >> 5);
    int lane = threadIdx.x & 31;
    int b = m & 127, l = m >> 7;
    int idx = bd[b * 512 + l];
    const float4* src = (const float4*)(emb + (size_t)idx * 256);
    float4* dst = (float4*)(d_x + (size_t)m * 256);
    dst[lane] = src[lane];
    dst[lane + 32] = src[lane + 32];
}

// ---------------- K1b: input projection SGEMM (f32x2) ----------------
__global__ void __launch_bounds__(256) k_gemm(const float* __restrict__ wf,
                                              const float* __restrict__ wb,
                                              const float* __restrict__ bf,
                                              const float* __restrict__ bb) {
    __shared__ float As[16][128];
    __shared__ float Bs[16][128];
    int tid = threadIdx.x;
    int m0 = blockIdx.x * 128;
    int n0 = blockIdx.y * 128;
    int dir = n0 >> 10;
    int nloc0 = n0 & 1023;
    const float* W  = dir ? wb : wf;
    const float* Bv = dir ? bb : bf;

    int lm = tid >> 1;
    int lk = (tid & 1) * 8;
    int tm = (tid & 15) * 8;
    int tn = (tid >> 4) * 8;

    float bias[8];
#pragma unroll
    for (int j = 0; j < 8; j++) bias[j] = Bv[nloc0 + tn + j];

    ull acc[4][8];
#pragma unroll
    for (int i = 0; i < 4; i++)
#pragma unroll
        for (int j = 0; j < 8; j++) acc[i][j] = 0ull;

    for (int k0 = 0; k0 < 256; k0 += 16) {
        float4 a0 = *(const float4*)(d_x + (size_t)(m0 + lm) * 256 + k0 + lk);
        float4 a1 = *(const float4*)(d_x + (size_t)(m0 + lm) * 256 + k0 + lk + 4);
        float4 b0 = *(const float4*)(W + (size_t)(nloc0 + lm) * 256 + k0 + lk);
        float4 b1 = *(const float4*)(W + (size_t)(nloc0 + lm) * 256 + k0 + lk + 4);
        __syncthreads();
        As[lk + 0][lm] = a0.x; As[lk + 1][lm] = a0.y; As[lk + 2][lm] = a0.z; As[lk + 3][lm] = a0.w;
        As[lk + 4][lm] = a1.x; As[lk + 5][lm] = a1.y; As[lk + 6][lm] = a1.z; As[lk + 7][lm] = a1.w;
        Bs[lk + 0][lm] = b0.x; Bs[lk + 1][lm] = b0.y; Bs[lk + 2][lm] = b0.z; Bs[lk + 3][lm] = b0.w;
        Bs[lk + 4][lm] = b1.x; Bs[lk + 5][lm] = b1.y; Bs[lk + 6][lm] = b1.z; Bs[lk + 7][lm] = b1.w;
        __syncthreads();
#pragma unroll
        for (int k = 0; k < 16; k++) {
            ull a2[4];
#pragma unroll
            for (int i = 0; i < 4; i++) a2[i] = *(const ull*)&As[k][tm + 2 * i];
            float4 w0 = *(const float4*)&Bs[k][tn];
            float4 w1 = *(const float4*)&Bs[k][tn + 4];
            ull b2[8];
            b2[0] = pack2f(w0.x, w0.x); b2[1] = pack2f(w0.y, w0.y);
            b2[2] = pack2f(w0.z, w0.z); b2[3] = pack2f(w0.w, w0.w);
            b2[4] = pack2f(w1.x, w1.x); b2[5] = pack2f(w1.y, w1.y);
            b2[6] = pack2f(w1.z, w1.z); b2[7] = pack2f(w1.w, w1.w);
#pragma unroll
            for (int i = 0; i < 4; i++)
#pragma unroll
                for (int j = 0; j < 8; j++) acc[i][j] = fma2(a2[i], b2[j], acc[i][j]);
        }
    }
#pragma unroll
    for (int i = 0; i < 4; i++) {
        float r0[8], r1[8];
#pragma unroll
        for (int j = 0; j < 8; j++) {
            float2 p = unpack2(acc[i][j]);
            r0[j] = p.x + bias[j];
            r1[j] = p.y + bias[j];
        }
        float* p0 = d_gx + ((size_t)dir * 65536 + (m0 + tm + 2 * i)) * 1024 + nloc0 + tn;
        float* p1 = p0 + 1024;
        *(float4*)(p0)     = make_float4(r0[0], r0[1], r0[2], r0[3]);
        *(float4*)(p0 + 4) = make_float4(r0[4], r0[5], r0[6], r0[7]);
        *(float4*)(p1)     = make_float4(r1[0], r1[1], r1[2], r1[3]);
        *(float4*)(p1 + 4) = make_float4(r1[4], r1[5], r1[6], r1[7]);
    }
}

// ---------------- K2: LSTM recurrence, tensor-core, cluster-of-2 k-split ----------------
// grid 64 = 32 clusters x 2. Per cluster: 8 batch rows, M=16 mma tile (8 pad rows = 0).
// dynamic smem layout:
#define HPITCH   528                      // 256 bf16 + 16B pad -> conflict-free ldmatrix
#define HBUFB    8448                     // 16 rows * 528
#define OFF_PRE  16896                    // local partial preacts fp32 [8][1032]
#define PREP     1032
#define OFF_PRE2 49920                    // peer partials bf16x2 [2][8][512] u32
#define OFF_MBAR 82688
#define SMEM_SZ  82704

__global__ void __launch_bounds__(512, 1) __cluster_dims__(2, 1, 1) k_recur() {
    extern __shared__ char sm[];
    float*    preL = (float*)(sm + OFF_PRE);
    unsigned* pre2 = (unsigned*)(sm + OFF_PRE2);
    ull*      mbar = (ull*)(sm + OFF_MBAR);

    int tid = threadIdx.x;
    unsigned rank;
    asm("mov.u32 %0, %%cluster_ctarank;" : "=r"(rank));
    int cid = blockIdx.x >> 1;
    int dir = cid >> 4;
    int b0 = (cid & 15) * 8;
    int lane = tid & 31, w = tid >> 5;

    const uint4* Wp = d_whh2 + ((size_t)((dir * 2 + (int)rank) * 16 + w)) * 1024;

    // zero both h buffers (incl. pad rows)
    for (int i = tid; i < 16896 / 4; i += 512) ((unsigned*)sm)[i] = 0u;
    if (tid == 0) {
        asm volatile("mbarrier.init.shared.b64 [%0], 1;" :: "r"(smem_u32(&mbar[0])) : "memory");
        asm volatile("mbarrier.init.shared.b64 [%0], 1;" :: "r"(smem_u32(&mbar[1])) : "memory");
    }
    __syncthreads();
    asm volatile("barrier.cluster.arrive.aligned;" ::: "memory");
    asm volatile("barrier.cluster.wait.aligned;" ::: "memory");

    unsigned peer = rank ^ 1u;
    unsigned my_m0 = smem_u32(&mbar[0]), my_m1 = smem_u32(&mbar[1]);
    unsigned pm0 = mapa_u32(my_m0, peer), pm1 = mapa_u32(my_m1, peer);
    unsigned ppre2 = mapa_u32(smem_u32(pre2), peer);
    unsigned hsm = smem_u32(sm);

    // ldmatrix per-lane row address (row = lane&15, k-offset by lane>>4)
    unsigned abase0 = hsm + (unsigned)(lane & 15) * HPITCH + rank * 256u + ((unsigned)(lane >> 4) << 4);

    int j = tid & 255, bset = tid >> 8;           // cell-update role
    int bE = lane >> 2;                            // epilogue real row 0..7
    int nbase = w * 64 + (lane & 3) * 2;

    float cc[4] = {0.f, 0.f, 0.f, 0.f};
    const float* gxb = d_gx + (size_t)dir * 65536 * 1024;
    int buf = 0;

    for (int step = 0; step < 512; step++) {
        int l = dir ? (511 - step) : step;

        // gx for cell role, fully coalesced; consumed after the matvec
        float gv[4][4];
        const float* gxr = gxb + ((size_t)l * 128 + b0 + bset * 4) * 1024;
#pragma unroll
        for (int q = 0; q < 4; q++) {
            const float* p = gxr + q * 1024;
            gv[q][0] = __ldg(p + j);       gv[q][1] = __ldg(p + 256 + j);
            gv[q][2] = __ldg(p + 512 + j); gv[q][3] = __ldg(p + 768 + j);
        }

        // ---- tensor-core matvec: C[16,1024-slice] += h[16,128] * W^T ----
        float c[8][4];
#pragma unroll
        for (int t = 0; t < 8; t++)
#pragma unroll
            for (int r = 0; r < 4; r++) c[t][r] = 0.f;

        unsigned abase = abase0 + (unsigned)buf * HBUFB;
        unsigned a[2][4];
        uint4 wq[2][4];
        LDSM4(a[0], abase);
#pragma unroll
        for (int p = 0; p < 4; p++) wq[0][p] = Wp[p * 32 + lane];
#pragma unroll
        for (int kt = 0; kt < 8; kt++) {
            int cb = kt & 1, nb = cb ^ 1;
            if (kt < 7) {
#pragma unroll
                for (int p = 0; p < 4; p++) wq[nb][p] = Wp[(kt + 1) * 128 + p * 32 + lane];
                LDSM4(a[nb], abase + (unsigned)(kt + 1) * 32);
            }
#pragma unroll
            for (int p = 0; p < 4; p++) {
                MMA_BF16(c[2 * p],     a[cb], wq[cb][p].x, wq[cb][p].y);
                MMA_BF16(c[2 * p + 1], a[cb], wq[cb][p].z, wq[cb][p].w);
            }
        }

        // ---- epilogue: local fp32 partial + ship bf16x2 to peer ----
#pragma unroll
        for (int nt = 0; nt < 8; nt++) {
            int n = nbase + nt * 8;
            *(float2*)&preL[bE * PREP + n] = make_float2(c[nt][0], c[nt][1]);
            unsigned u;
            asm("cvt.rn.bf16x2.f32 %0,%1,%2;" : "=r"(u) : "f"(c[nt][1]), "f"(c[nt][0]));
            unsigned ad = ppre2 + (((unsigned)buf * 8 + (unsigned)bE) * 512 + ((unsigned)n >> 1)) * 4;
            asm volatile("st.shared::cluster.u32 [%0],%1;" :: "r"(ad), "r"(u) : "memory");
        }
        __syncthreads();
        if (tid == 0) {
            unsigned pm = (step & 1) ? pm1 : pm0;
            asm volatile("mbarrier.arrive.release.cluster.shared::cluster.b64 _, [%0];"
                         :: "r"(pm) : "memory");
        }
        {
            unsigned mm = (step & 1) ? my_m1 : my_m0;
            unsigned ph = (unsigned)(step >> 1) & 1u;
            unsigned done;
            asm volatile("{\n\t.reg .pred p;\n\t"
                         "mbarrier.try_wait.parity.acquire.cluster.shared::cta.b64 p, [%1], %2;\n\t"
                         "selp.b32 %0, 1, 0, p;\n\t}"
                         : "=r"(done) : "r"(mm), "r"(ph) : "memory");
            while (!done) {
                asm volatile("{\n\t.reg .pred p;\n\t"
                             "mbarrier.try_wait.parity.acquire.cluster.shared::cta.b64 p, [%1], %2, 0x989680;\n\t"
                             "selp.b32 %0, 1, 0, p;\n\t}"
                             : "=r"(done) : "r"(mm), "r"(ph) : "memory");
            }
        }

        // ---- cell update (redundant across pair) ----
        int hlf = j & 1;
#pragma unroll
        for (int q = 0; q < 4; q++) {
            int b = bset * 4 + q;
            const unsigned* p2 = pre2 + ((unsigned)buf * 8 + b) * 512 + (j >> 1);
            const float* pl = preL + b * PREP;
            float pi = pl[j]       + bfhalf(p2[0],   hlf) + gv[q][0];
            float pf = pl[256 + j] + bfhalf(p2[128], hlf) + gv[q][1];
            float pg = pl[512 + j] + bfhalf(p2[256], hlf) + gv[q][2];
            float po = pl[768 + j] + bfhalf(p2[384], hlf) + gv[q][3];
            float i_ = sigf(pi), f_ = sigf(pf), g_ = tanhx(pg), o_ = sigf(po);
            cc[q] = f_ * cc[q] + i_ * g_;
            float hv = o_ * tanhx(cc[q]);
            *(unsigned short*)(sm + (buf ^ 1) * HBUFB + b * HPITCH + j * 2) =
                __bfloat16_as_ushort(__float2bfloat16(hv));
            if (bset == (int)rank)
                d_hcat[((size_t)(b0 + b) * 512 + l) * 512 + dir * 256 + j] = hv;
        }
        buf ^= 1;
        __syncthreads();
    }

    asm volatile("barrier.cluster.arrive.aligned;" ::: "memory");
    asm volatile("barrier.cluster.wait.aligned;" ::: "memory");
}

// ---------------- K3: emission = hcat @ w_cls^T + b_cls ----------------
__global__ void __launch_bounds__(256) k_emis(const float* __restrict__ wcls,
                                              const float* __restrict__ bcls) {
    __shared__ float wc[16 * 512];
    int tid = threadIdx.x;
    for (int i = tid; i < 16 * 512 / 4; i += 256)
        ((float4*)wc)[i] = ((const float4*)wcls)[i];
    __syncthreads();
    int m = blockIdx.x * 8 + (tid >> 5);
    int lane = tid & 31;
    float acc[16];
#pragma unroll
    for (int t = 0; t < 16; t++) acc[t] = 0.f;
    const float* hp = d_hcat + (size_t)m * 512;
#pragma unroll
    for (int it = 0; it < 4; it++) {
        int k = it * 128 + lane * 4;
        float4 h4 = *(const float4*)(hp + k);
#pragma unroll
        for (int t = 0; t < 16; t++) {
            float4 w4 = *(const float4*)(wc + t * 512 + k);
            acc[t] += h4.x * w4.x + h4.y * w4.y + h4.z * w4.z + h4.w * w4.w;
        }
    }
#pragma unroll
    for (int t = 0; t < 16; t++)
#pragma unroll
        for (int off = 16; off; off >>= 1) acc[t] += __shfl_xor_sync(0xffffffffu, acc[t], off);
    if (lane < 16) {
        float v = acc[0];
#pragma unroll
        for (int t = 1; t < 16; t++) v = (lane == t) ? acc[t] : v;
        d_emission[(size_t)m * 16 + lane] = v + bcls[lane];
    }
}

// ---------------- K4: CRF golden + forward (1 warp / batch row) ----------------
__global__ void k_crf(const int* __restrict__ tag, const float* __restrict__ trans) {
    __shared__ float tr[256];
    int b = blockIdx.x, lane = threadIdx.x;
    for (int i = lane; i < 256; i += 32) tr[i] = trans[i];
    __syncwarp();
    int cur = lane & 15;
    float tcol[16];
#pragma unroll
    for (int p = 0; p < 16; p++) tcol[p] = tr[p * 16 + cur];
    const int* tg = tag + b * 512;
    int len = 0;
    for (int l2 = lane; l2 < 512; l2 += 32) len += (tg[l2] != 0);
#pragma unroll
    for (int off = 16; off; off >>= 1) len += __shfl_xor_sync(0xffffffffu, len, off);

    const float* em = d_emission + (size_t)b * 512 * 16;
    float gsum = 0.f;
    for (int l2 = lane; l2 < 512; l2 += 32)
        if (l2 < len) {
            int t = tg[l2];
            int pv = l2 ? tg[l2 - 1] : 14;       // START=14
            gsum += em[l2 * 16 + t] + tr[pv * 16 + t];
        }
#pragma unroll
    for (int off = 16; off; off >>= 1) gsum += __shfl_xor_sync(0xffffffffu, gsum, off);

    float score = em[cur] + tr[14 * 16 + cur];
    for (int t = 1; t < 512; t++) {
        float m = -1e30f, s = 0.f;
#pragma unroll
        for (int p = 0; p < 16; p++) {
            float v = __shfl_sync(0xffffffffu, score, p) + tcol[p];
            float mn = fmaxf(m, v);
            s = s * __expf(m - mn) + __expf(v - mn);
            m = mn;
        }
        float ns = em[t * 16 + cur] + m + __logf(s);
        score = (t < len) ? ns : score;
    }
    if (lane == 15) atomicAdd(&d_acc[0], (double)score);  // END=15
    if (lane == 0)  atomicAdd(&d_acc[1], (double)gsum);
}

__global__ void k_final(float* out) {
    out[0] = (float)((d_acc[0] - d_acc[1]) / 128.0);
}

// ---------------- launch ----------------
extern "C" void kernel_launch(void* const* d_in, const int* in_sizes, int n_in,
                              void* d_out, int out_size) {
    const int*   batch_data = (const int*)d_in[0];
    const int*   batch_tag  = (const int*)d_in[1];
    const float* emb        = (const float*)d_in[2];
    const float* w_ih_f     = (const float*)d_in[3];
    const float* w_hh_f     = (const float*)d_in[4];
    const float* b_f        = (const float*)d_in[5];
    const float* w_ih_b     = (const float*)d_in[6];
    const float* w_hh_b     = (const float*)d_in[7];
    const float* b_b        = (const float*)d_in[8];
    const float* w_cls      = (const float*)d_in[9];
    const float* b_cls      = (const float*)d_in[10];
    const float* transition = (const float*)d_in[11];

    cudaFuncSetAttribute(k_recur, cudaFuncAttributeMaxDynamicSharedMemorySize, SMEM_SZ);

    k_prep<<<256, 256>>>(w_hh_f, w_hh_b);
    k_gather<<<8192, 256>>>(batch_data, emb);
    k_gemm<<<dim3(512, 16), 256>>>(w_ih_f, w_ih_b, b_f, b_b);
    k_recur<<<64, 512, SMEM_SZ>>>();
    k_emis<<<8192, 256>>>(w_cls, b_cls);
    k_crf<<<128, 32>>>(batch_tag, transition);
    k_final<<<1, 1>>>((float*)d_out);
}

// round 6
// speedup vs baseline: 3.3020x; 1.2175x over previous
#include <cuda_runtime.h>
#include <cuda_bf16.h>

typedef unsigned long long ull;

// ---------------- device scratch (no runtime allocation) ----------------
__device__ float d_x[(size_t)65536 * 256];            // gathered embeddings [m][256], m = l*128+b
__device__ float d_gx[(size_t)2 * 65536 * 1024];      // input gate preacts [dir][m][1024]
__device__ float d_hcat[(size_t)128 * 512 * 512];     // [b][l][hf|hb]
__device__ float d_emission[(size_t)65536 * 16];      // [b*512+l][16]
__device__ uint4 d_whh2[65536];                       // W_hh mma B fragments [dir][gate][w][kt][lane]
__device__ double d_acc[2];                           // [all_path, golden]

// ---------------- f32x2 helpers (used by k_gemm) ----------------
__device__ __forceinline__ ull fma2(ull a, ull b, ull c) {
    ull d; asm("fma.rn.f32x2 %0,%1,%2,%3;" : "=l"(d) : "l"(a), "l"(b), "l"(c)); return d;
}
__device__ __forceinline__ ull pack2f(float x, float y) {
    ull r; asm("mov.b64 %0,{%1,%2};" : "=l"(r) : "f"(x), "f"(y)); return r;
}
__device__ __forceinline__ float2 unpack2(ull v) {
    float x, y; asm("mov.b64 {%0,%1},%2;" : "=f"(x), "=f"(y) : "l"(v));
    float2 r; r.x = x; r.y = y; return r;
}
__device__ __forceinline__ float bfhalf(unsigned u, int hi) {
    return __uint_as_float(hi ? (u & 0xffff0000u) : (u << 16));
}
__device__ __forceinline__ float sigf(float x) { return 1.f / (1.f + __expf(-x)); }
__device__ __forceinline__ float tanhx(float x) { return 2.f / (1.f + __expf(-2.f * x)) - 1.f; }

__device__ __forceinline__ unsigned smem_u32(const void* p) {
    unsigned a;
    asm("{ .reg .u64 t; cvta.to.shared.u64 t, %1; cvt.u32.u64 %0, t; }" : "=r"(a) : "l"(p));
    return a;
}
__device__ __forceinline__ unsigned mapa_u32(unsigned a, unsigned rank) {
    unsigned d; asm("mapa.shared::cluster.u32 %0,%1,%2;" : "=r"(d) : "r"(a), "r"(rank));
    return d;
}

// mma + ldmatrix macros
#define MMA_BF16(C, A, B0, B1)                                                          \
    asm volatile("mma.sync.aligned.m16n8k16.row.col.f32.bf16.bf16.f32 "                 \
                 "{%0,%1,%2,%3},{%4,%5,%6,%7},{%8,%9},{%0,%1,%2,%3};"                   \
                 : "+f"((C)[0]), "+f"((C)[1]), "+f"((C)[2]), "+f"((C)[3])               \
                 : "r"((A)[0]), "r"((A)[1]), "r"((A)[2]), "r"((A)[3]),                  \
                   "r"(B0), "r"(B1))
#define LDSM4(R, ADDR)                                                                  \
    asm volatile("ldmatrix.sync.aligned.m8n8.x4.shared.b16 {%0,%1,%2,%3},[%4];"         \
                 : "=r"((R)[0]), "=r"((R)[1]), "=r"((R)[2]), "=r"((R)[3]) : "r"(ADDR))

// ---------------- K0: prep (weights -> gate-split mma B-fragment layout) ----------------
__device__ __forceinline__ unsigned pkbf(const float* s, int n, int k) {
    unsigned short lo = __bfloat16_as_ushort(__float2bfloat16(s[n * 256 + k]));
    unsigned short hi = __bfloat16_as_ushort(__float2bfloat16(s[n * 256 + k + 1]));
    return ((unsigned)hi << 16) | (unsigned)lo;
}
__global__ void k_prep(const float* __restrict__ whf, const float* __restrict__ whb) {
    int e = blockIdx.x * 256 + threadIdx.x;   // 65536
    int lane = e & 31, kt = (e >> 5) & 15, w = (e >> 9) & 15;
    int g = (e >> 13) & 3, dir = (e >> 15) & 1;
    const float* src = dir ? whb : whf;
    int row = g * 256 + w * 16 + (lane >> 2);
    int k0 = kt * 16 + (lane & 3) * 2;
    uint4 v;
    v.x = pkbf(src, row, k0);
    v.y = pkbf(src, row, k0 + 8);
    v.z = pkbf(src, row + 8, k0);
    v.w = pkbf(src, row + 8, k0 + 8);
    d_whh2[e] = v;
    if (e < 2) d_acc[e] = 0.0;
}

// ---------------- K1a: embedding gather ----------------
__global__ void k_gather(const int* __restrict__ bd, const float* __restrict__ emb) {
    int m = blockIdx.x * 8 + (threadIdx.x >> 5);
    int lane = threadIdx.x & 31;
    int b = m & 127, l = m >> 7;
    int idx = bd[b * 512 + l];
    const float4* src = (const float4*)(emb + (size_t)idx * 256);
    float4* dst = (float4*)(d_x + (size_t)m * 256);
    dst[lane] = src[lane];
    dst[lane + 32] = src[lane + 32];
}

// ---------------- K1b: input projection SGEMM (f32x2) ----------------
__global__ void __launch_bounds__(256) k_gemm(const float* __restrict__ wf,
                                              const float* __restrict__ wb,
                                              const float* __restrict__ bf,
                                              const float* __restrict__ bb) {
    __shared__ float As[16][128];
    __shared__ float Bs[16][128];
    int tid = threadIdx.x;
    int m0 = blockIdx.x * 128;
    int n0 = blockIdx.y * 128;
    int dir = n0 >> 10;
    int nloc0 = n0 & 1023;
    const float* W  = dir ? wb : wf;
    const float* Bv = dir ? bb : bf;

    int lm = tid >> 1;
    int lk = (tid & 1) * 8;
    int tm = (tid & 15) * 8;
    int tn = (tid >> 4) * 8;

    float bias[8];
#pragma unroll
    for (int j = 0; j < 8; j++) bias[j] = Bv[nloc0 + tn + j];

    ull acc[4][8];
#pragma unroll
    for (int i = 0; i < 4; i++)
#pragma unroll
        for (int j = 0; j < 8; j++) acc[i][j] = 0ull;

    for (int k0 = 0; k0 < 256; k0 += 16) {
        float4 a0 = *(const float4*)(d_x + (size_t)(m0 + lm) * 256 + k0 + lk);
        float4 a1 = *(const float4*)(d_x + (size_t)(m0 + lm) * 256 + k0 + lk + 4);
        float4 b0 = *(const float4*)(W + (size_t)(nloc0 + lm) * 256 + k0 + lk);
        float4 b1 = *(const float4*)(W + (size_t)(nloc0 + lm) * 256 + k0 + lk + 4);
        __syncthreads();
        As[lk + 0][lm] = a0.x; As[lk + 1][lm] = a0.y; As[lk + 2][lm] = a0.z; As[lk + 3][lm] = a0.w;
        As[lk + 4][lm] = a1.x; As[lk + 5][lm] = a1.y; As[lk + 6][lm] = a1.z; As[lk + 7][lm] = a1.w;
        Bs[lk + 0][lm] = b0.x; Bs[lk + 1][lm] = b0.y; Bs[lk + 2][lm] = b0.z; Bs[lk + 3][lm] = b0.w;
        Bs[lk + 4][lm] = b1.x; Bs[lk + 5][lm] = b1.y; Bs[lk + 6][lm] = b1.z; Bs[lk + 7][lm] = b1.w;
        __syncthreads();
#pragma unroll
        for (int k = 0; k < 16; k++) {
            ull a2[4];
#pragma unroll
            for (int i = 0; i < 4; i++) a2[i] = *(const ull*)&As[k][tm + 2 * i];
            float4 w0 = *(const float4*)&Bs[k][tn];
            float4 w1 = *(const float4*)&Bs[k][tn + 4];
            ull b2[8];
            b2[0] = pack2f(w0.x, w0.x); b2[1] = pack2f(w0.y, w0.y);
            b2[2] = pack2f(w0.z, w0.z); b2[3] = pack2f(w0.w, w0.w);
            b2[4] = pack2f(w1.x, w1.x); b2[5] = pack2f(w1.y, w1.y);
            b2[6] = pack2f(w1.z, w1.z); b2[7] = pack2f(w1.w, w1.w);
#pragma unroll
            for (int i = 0; i < 4; i++)
#pragma unroll
                for (int j = 0; j < 8; j++) acc[i][j] = fma2(a2[i], b2[j], acc[i][j]);
        }
    }
#pragma unroll
    for (int i = 0; i < 4; i++) {
        float r0[8], r1[8];
#pragma unroll
        for (int j = 0; j < 8; j++) {
            float2 p = unpack2(acc[i][j]);
            r0[j] = p.x + bias[j];
            r1[j] = p.y + bias[j];
        }
        float* p0 = d_gx + ((size_t)dir * 65536 + (m0 + tm + 2 * i)) * 1024 + nloc0 + tn;
        float* p1 = p0 + 1024;
        *(float4*)(p0)     = make_float4(r0[0], r0[1], r0[2], r0[3]);
        *(float4*)(p0 + 4) = make_float4(r0[4], r0[5], r0[6], r0[7]);
        *(float4*)(p1)     = make_float4(r1[0], r1[1], r1[2], r1[3]);
        *(float4*)(p1 + 4) = make_float4(r1[4], r1[5], r1[6], r1[7]);
    }
}

// ---------------- K2: LSTM recurrence, cluster-of-4 gate-split, smem weights ----------------
#define HPITCH   528
#define HBUFB    8448                    // 16 rows * 528
#define OFF_H    131072                  // weights occupy [0, 131072)
#define OFF_RECV 147968                  // OFF_H + 2*HBUFB = 131072+16896
#define OFF_MBAR 152064                  // OFF_RECV + 4096
#define SMEM_SZ  152080

__global__ void __launch_bounds__(512, 1) __cluster_dims__(4, 1, 1) k_recur() {
    extern __shared__ char sm[];
    int tid = threadIdx.x;
    unsigned rank;
    asm("mov.u32 %0, %%cluster_ctarank;" : "=r"(rank));
    int cid = blockIdx.x >> 2;
    int dir = cid >> 4;
    int b0 = (cid & 15) * 8;
    int lane = tid & 31, w = tid >> 5;

    // load this gate's weights (128 KB) into smem once
    const uint4* wg = d_whh2 + ((size_t)(dir * 4 + (int)rank)) * 8192;
    uint4* smW = (uint4*)sm;
    for (int i = tid; i < 8192; i += 512) smW[i] = wg[i];
    // zero both h buffers (incl. pad rows)
    for (int i = tid; i < 2 * HBUFB / 4; i += 512) ((unsigned*)(sm + OFF_H))[i] = 0u;

    ull* mbar = (ull*)(sm + OFF_MBAR);
    if (tid == 0) {
        asm volatile("mbarrier.init.shared.b64 [%0], 3;" :: "r"(smem_u32(&mbar[0])) : "memory");
        asm volatile("mbarrier.init.shared.b64 [%0], 3;" :: "r"(smem_u32(&mbar[1])) : "memory");
    }
    __syncthreads();
    asm volatile("barrier.cluster.arrive.aligned;" ::: "memory");
    asm volatile("barrier.cluster.wait.aligned;" ::: "memory");

    unsigned recv_l = smem_u32(sm + OFF_RECV);
    unsigned h_l    = smem_u32(sm + OFF_H);
    unsigned b1_l   = smem_u32(&mbar[0]);
    unsigned b2_l   = smem_u32(&mbar[1]);
    unsigned rh[4], rb1[4], rb2[4];
#pragma unroll
    for (int r = 0; r < 4; r++) {
        rh[r]  = mapa_u32(h_l, r);
        rb1[r] = mapa_u32(b1_l, r);
        rb2[r] = mapa_u32(b2_l, r);
    }

    // matvec roles
    unsigned abase0 = h_l + (unsigned)(lane & 15) * HPITCH + ((unsigned)(lane >> 4) << 4);
    int bE = lane >> 2;
    unsigned rdst = (unsigned)(bE >> 1);
    int qE = bE & 1;
    int nl = w * 16 + (lane & 3) * 2;
    unsigned dst0 = mapa_u32(recv_l, rdst) + ((unsigned)rank * 256 + qE * 128 + (nl >> 1)) * 4;
    const uint4* Wme = smW + w * 512 + lane;   // + kt*32

    // cell roles
    int q = tid >> 8, j = tid & 255;
    int b_own = b0 + (int)rank * 2 + q;
    int hrow = (int)rank * 2 + q;
    const unsigned* rcv = (const unsigned*)(sm + OFF_RECV) + q * 128 + (j >> 1);
    int hlf = j & 1;

    float cc = 0.f;
    const float* gxb = d_gx + (size_t)dir * 65536 * 1024;
    int buf = 0;

    for (int step = 0; step < 512; step++) {
        int l = dir ? (511 - step) : step;
        const float* gxp = gxb + ((size_t)l * 128 + b_own) * 1024 + j;
        float g0 = __ldg(gxp), g1 = __ldg(gxp + 256), g2 = __ldg(gxp + 512), g3 = __ldg(gxp + 768);

        // ---- matvec: this gate's 256 preacts for 8 batches ----
        float c0[4] = {0.f, 0.f, 0.f, 0.f}, c1[4] = {0.f, 0.f, 0.f, 0.f};
        unsigned abase = abase0 + (unsigned)buf * HBUFB;
#pragma unroll
        for (int kt = 0; kt < 16; kt++) {
            unsigned a[4];
            LDSM4(a, abase + (unsigned)kt * 32);
            uint4 bq = Wme[kt * 32];
            MMA_BF16(c0, a, bq.x, bq.y);
            MMA_BF16(c1, a, bq.z, bq.w);
        }
        // ship preacts (bf16x2) to batch-owner CTA (incl. self)
        unsigned u0, u1;
        asm("cvt.rn.bf16x2.f32 %0,%1,%2;" : "=r"(u0) : "f"(c0[1]), "f"(c0[0]));
        asm("cvt.rn.bf16x2.f32 %0,%1,%2;" : "=r"(u1) : "f"(c1[1]), "f"(c1[0]));
        asm volatile("st.shared::cluster.u32 [%0],%1;" :: "r"(dst0), "r"(u0) : "memory");
        asm volatile("st.shared::cluster.u32 [%0],%1;" :: "r"(dst0 + 16), "r"(u1) : "memory");
        __syncthreads();
        if (tid == 0) {
#pragma unroll
            for (int r = 0; r < 4; r++)
                if (r != (int)rank)
                    asm volatile("mbarrier.arrive.release.cluster.shared::cluster.b64 _, [%0];"
                                 :: "r"(rb1[r]) : "memory");
        }
        {
            unsigned ph = (unsigned)step & 1u, done;
            asm volatile("{\n\t.reg .pred p;\n\t"
                         "mbarrier.try_wait.parity.acquire.cluster.shared::cta.b64 p, [%1], %2;\n\t"
                         "selp.b32 %0, 1, 0, p;\n\t}"
                         : "=r"(done) : "r"(b1_l), "r"(ph) : "memory");
            while (!done)
                asm volatile("{\n\t.reg .pred p;\n\t"
                             "mbarrier.try_wait.parity.acquire.cluster.shared::cta.b64 p, [%1], %2, 0x989680;\n\t"
                             "selp.b32 %0, 1, 0, p;\n\t}"
                             : "=r"(done) : "r"(b1_l), "r"(ph) : "memory");
        }

        // ---- cell update for own 2 batch rows ----
        float pi = bfhalf(rcv[0],   hlf) + g0;
        float pf = bfhalf(rcv[256], hlf) + g1;
        float pg = bfhalf(rcv[512], hlf) + g2;
        float po = bfhalf(rcv[768], hlf) + g3;
        float i_ = sigf(pi), f_ = sigf(pf), g_ = tanhx(pg), o_ = sigf(po);
        cc = f_ * cc + i_ * g_;
        float hv = o_ * tanhx(cc);
        d_hcat[((size_t)b_own * 512 + l) * 512 + dir * 256 + j] = hv;

        // ---- broadcast new h row to all 4 CTAs ----
        float hn = __shfl_down_sync(0xffffffffu, hv, 1);
        if (!hlf) {
            unsigned hu;
            asm("cvt.rn.bf16x2.f32 %0,%1,%2;" : "=r"(hu) : "f"(hn), "f"(hv));
            unsigned off = (unsigned)(buf ^ 1) * HBUFB + (unsigned)hrow * HPITCH + (unsigned)j * 2;
#pragma unroll
            for (int r = 0; r < 4; r++)
                asm volatile("st.shared::cluster.u32 [%0],%1;" :: "r"(rh[r] + off), "r"(hu) : "memory");
        }
        __syncthreads();
        if (tid == 0) {
#pragma unroll
            for (int r = 0; r < 4; r++)
                if (r != (int)rank)
                    asm volatile("mbarrier.arrive.release.cluster.shared::cluster.b64 _, [%0];"
                                 :: "r"(rb2[r]) : "memory");
        }
        {
            unsigned ph = (unsigned)step & 1u, done;
            asm volatile("{\n\t.reg .pred p;\n\t"
                         "mbarrier.try_wait.parity.acquire.cluster.shared::cta.b64 p, [%1], %2;\n\t"
                         "selp.b32 %0, 1, 0, p;\n\t}"
                         : "=r"(done) : "r"(b2_l), "r"(ph) : "memory");
            while (!done)
                asm volatile("{\n\t.reg .pred p;\n\t"
                             "mbarrier.try_wait.parity.acquire.cluster.shared::cta.b64 p, [%1], %2, 0x989680;\n\t"
                             "selp.b32 %0, 1, 0, p;\n\t}"
                             : "=r"(done) : "r"(b2_l), "r"(ph) : "memory");
        }
        buf ^= 1;
    }

    asm volatile("barrier.cluster.arrive.aligned;" ::: "memory");
    asm volatile("barrier.cluster.wait.aligned;" ::: "memory");
}

// ---------------- K3: emission = hcat @ w_cls^T + b_cls ----------------
__global__ void __launch_bounds__(256) k_emis(const float* __restrict__ wcls,
                                              const float* __restrict__ bcls) {
    __shared__ float wc[16 * 512];
    int tid = threadIdx.x;
    for (int i = tid; i < 16 * 512 / 4; i += 256)
        ((float4*)wc)[i] = ((const float4*)wcls)[i];
    __syncthreads();
    int m = blockIdx.x * 8 + (tid >> 5);
    int lane = tid & 31;
    float acc[16];
#pragma unroll
    for (int t = 0; t < 16; t++) acc[t] = 0.f;
    const float* hp = d_hcat + (size_t)m * 512;
#pragma unroll
    for (int it = 0; it < 4; it++) {
        int k = it * 128 + lane * 4;
        float4 h4 = *(const float4*)(hp + k);
#pragma unroll
        for (int t = 0; t < 16; t++) {
            float4 w4 = *(const float4*)(wc + t * 512 + k);
            acc[t] += h4.x * w4.x + h4.y * w4.y + h4.z * w4.z + h4.w * w4.w;
        }
    }
#pragma unroll
    for (int t = 0; t < 16; t++)
#pragma unroll
        for (int off = 16; off; off >>= 1) acc[t] += __shfl_xor_sync(0xffffffffu, acc[t], off);
    if (lane < 16) {
        float v = acc[0];
#pragma unroll
        for (int t = 1; t < 16; t++) v = (lane == t) ? acc[t] : v;
        d_emission[(size_t)m * 16 + lane] = v + bcls[lane];
    }
}

// ---------------- K4: CRF golden + forward (1 warp / batch row) ----------------
__global__ void k_crf(const int* __restrict__ tag, const float* __restrict__ trans) {
    __shared__ float tr[256];
    int b = blockIdx.x, lane = threadIdx.x;
    for (int i = lane; i < 256; i += 32) tr[i] = trans[i];
    __syncwarp();
    int cur = lane & 15;
    float tcol[16];
#pragma unroll
    for (int p = 0; p < 16; p++) tcol[p] = tr[p * 16 + cur];
    const int* tg = tag + b * 512;
    int len = 0;
    for (int l2 = lane; l2 < 512; l2 += 32) len += (tg[l2] != 0);
#pragma unroll
    for (int off = 16; off; off >>= 1) len += __shfl_xor_sync(0xffffffffu, len, off);

    const float* em = d_emission + (size_t)b * 512 * 16;
    float gsum = 0.f;
    for (int l2 = lane; l2 < 512; l2 += 32)
        if (l2 < len) {
            int t = tg[l2];
            int pv = l2 ? tg[l2 - 1] : 14;       // START=14
            gsum += em[l2 * 16 + t] + tr[pv * 16 + t];
        }
#pragma unroll
    for (int off = 16; off; off >>= 1) gsum += __shfl_xor_sync(0xffffffffu, gsum, off);

    float score = em[cur] + tr[14 * 16 + cur];
    for (int t = 1; t < 512; t++) {
        float m = -1e30f, s = 0.f;
#pragma unroll
        for (int p = 0; p < 16; p++) {
            float v = __shfl_sync(0xffffffffu, score, p) + tcol[p];
            float mn = fmaxf(m, v);
            s = s * __expf(m - mn) + __expf(v - mn);
            m = mn;
        }
        float ns = em[t * 16 + cur] + m + __logf(s);
        score = (t < len) ? ns : score;
    }
    if (lane == 15) atomicAdd(&d_acc[0], (double)score);  // END=15
    if (lane == 0)  atomicAdd(&d_acc[1], (double)gsum);
}

__global__ void k_final(float* out) {
    out[0] = (float)((d_acc[0] - d_acc[1]) / 128.0);
}

// ---------------- launch ----------------
extern "C" void kernel_launch(void* const* d_in, const int* in_sizes, int n_in,
                              void* d_out, int out_size) {
    const int*   batch_data = (const int*)d_in[0];
    const int*   batch_tag  = (const int*)d_in[1];
    const float* emb        = (const float*)d_in[2];
    const float* w_ih_f     = (const float*)d_in[3];
    const float* w_hh_f     = (const float*)d_in[4];
    const float* b_f        = (const float*)d_in[5];
    const float* w_ih_b     = (const float*)d_in[6];
    const float* w_hh_b     = (const float*)d_in[7];
    const float* b_b        = (const float*)d_in[8];
    const float* w_cls      = (const float*)d_in[9];
    const float* b_cls      = (const float*)d_in[10];
    const float* transition = (const float*)d_in[11];

    cudaFuncSetAttribute(k_recur, cudaFuncAttributeMaxDynamicSharedMemorySize, SMEM_SZ);

    k_prep<<<256, 256>>>(w_hh_f, w_hh_b);
    k_gather<<<8192, 256>>>(batch_data, emb);
    k_gemm<<<dim3(512, 16), 256>>>(w_ih_f, w_ih_b, b_f, b_b);
    k_recur<<<128, 512, SMEM_SZ>>>();
    k_emis<<<8192, 256>>>(w_cls, b_cls);
    k_crf<<<128, 32>>>(batch_tag, transition);
    k_final<<<1, 1>>>((float*)d_out);
}

// round 7
// speedup vs baseline: 4.2408x; 1.2843x over previous
#include <cuda_runtime.h>
#include <cuda_bf16.h>

typedef unsigned long long ull;

// ---------------- device scratch (no runtime allocation) ----------------
__device__ __nv_bfloat16 d_xb[(size_t)65536 * 256];  // gathered embeddings bf16 [m][256]
__device__ float d_gx[(size_t)2 * 65536 * 1024];     // input gate preacts [dir][m][1024]
__device__ float d_hcat[(size_t)128 * 512 * 512];    // [b][l][hf|hb]
__device__ float d_emission[(size_t)65536 * 16];     // [b*512+l][16]
__device__ uint4 d_whh2[65536];                      // W_hh mma B fragments [dir][gate][w][kt][lane]
__device__ uint4 d_wih2[65536];                      // W_ih mma B fragments [dir][nt16][kt][lane]
__device__ double d_acc[2];                          // [all_path, golden]

// ---------------- helpers ----------------
__device__ __forceinline__ float bflo(unsigned w) { return __uint_as_float(w << 16); }
__device__ __forceinline__ float bfhi(unsigned w) { return __uint_as_float(w & 0xffff0000u); }
__device__ __forceinline__ float tanha(float x) {   // HW tanh (for sigmoids only)
    float r; asm("tanh.approx.f32 %0,%1;" : "=f"(r) : "f"(x)); return r;
}
__device__ __forceinline__ float sigt(float x) { return fmaf(tanha(0.5f * x), 0.5f, 0.5f); }
__device__ __forceinline__ float tanhe(float x) { return 2.f / (1.f + __expf(-2.f * x)) - 1.f; }

__device__ __forceinline__ unsigned smem_u32(const void* p) {
    unsigned a;
    asm("{ .reg .u64 t; cvta.to.shared.u64 t, %1; cvt.u32.u64 %0, t; }" : "=r"(a) : "l"(p));
    return a;
}
__device__ __forceinline__ unsigned mapa_u32(unsigned a, unsigned rank) {
    unsigned d; asm("mapa.shared::cluster.u32 %0,%1,%2;" : "=r"(d) : "r"(a), "r"(rank));
    return d;
}
__device__ __forceinline__ unsigned cvt_bf2(float hi, float lo) {
    unsigned u; asm("cvt.rn.bf16x2.f32 %0,%1,%2;" : "=r"(u) : "f"(hi), "f"(lo)); return u;
}

#define MMA_BF16(C, A, B0, B1)                                                          \
    asm volatile("mma.sync.aligned.m16n8k16.row.col.f32.bf16.bf16.f32 "                 \
                 "{%0,%1,%2,%3},{%4,%5,%6,%7},{%8,%9},{%0,%1,%2,%3};"                   \
                 : "+f"((C)[0]), "+f"((C)[1]), "+f"((C)[2]), "+f"((C)[3])               \
                 : "r"((A)[0]), "r"((A)[1]), "r"((A)[2]), "r"((A)[3]),                  \
                   "r"(B0), "r"(B1))
#define LDSM4(R, ADDR)                                                                  \
    asm volatile("ldmatrix.sync.aligned.m8n8.x4.shared.b16 {%0,%1,%2,%3},[%4];"         \
                 : "=r"((R)[0]), "=r"((R)[1]), "=r"((R)[2]), "=r"((R)[3]) : "r"(ADDR))

// ---------------- K0: prep (whh + wih fragments, zero acc) ----------------
__device__ __forceinline__ unsigned pkbf(const float* s, int n, int k) {
    unsigned short lo = __bfloat16_as_ushort(__float2bfloat16(s[n * 256 + k]));
    unsigned short hi = __bfloat16_as_ushort(__float2bfloat16(s[n * 256 + k + 1]));
    return ((unsigned)hi << 16) | (unsigned)lo;
}
__global__ void k_prep(const float* __restrict__ whf, const float* __restrict__ whb,
                       const float* __restrict__ wif, const float* __restrict__ wib) {
    int e = blockIdx.x * 256 + threadIdx.x;   // 0..131071
    if (e < 65536) {
        int lane = e & 31, kt = (e >> 5) & 15, w = (e >> 9) & 15;
        int g = (e >> 13) & 3, dir = (e >> 15) & 1;
        const float* src = dir ? whb : whf;
        int row = g * 256 + w * 16 + (lane >> 2);
        int k0 = kt * 16 + (lane & 3) * 2;
        uint4 v;
        v.x = pkbf(src, row, k0);     v.y = pkbf(src, row, k0 + 8);
        v.z = pkbf(src, row + 8, k0); v.w = pkbf(src, row + 8, k0 + 8);
        d_whh2[e] = v;
    } else {
        int f = e - 65536;
        int lane = f & 31, kt = (f >> 5) & 15, nt = (f >> 9) & 63, dir = (f >> 15) & 1;
        const float* src = dir ? wib : wif;
        int row = nt * 16 + (lane >> 2);
        int k0 = kt * 16 + (lane & 3) * 2;
        uint4 v;
        v.x = pkbf(src, row, k0);     v.y = pkbf(src, row, k0 + 8);
        v.z = pkbf(src, row + 8, k0); v.w = pkbf(src, row + 8, k0 + 8);
        d_wih2[f] = v;
    }
    if (e < 2) d_acc[e] = 0.0;
}

// ---------------- K1a: embedding gather (fp32 -> bf16) ----------------
__global__ void k_gather(const int* __restrict__ bd, const float* __restrict__ emb) {
    int m = blockIdx.x * 8 + (threadIdx.x >> 5);
    int lane = threadIdx.x & 31;
    int b = m & 127, l = m >> 7;
    int idx = bd[b * 512 + l];
    const float* src = emb + (size_t)idx * 256;
    unsigned* dst = (unsigned*)(d_xb + (size_t)m * 256);
#pragma unroll
    for (int t = 0; t < 4; t++) {
        int i = lane + t * 32;
        float2 v = *(const float2*)(src + 2 * i);
        dst[i] = cvt_bf2(v.y, v.x);
    }
}

// ---------------- K1b: input projection via mma.sync bf16 ----------------
#define GSM 67584
__global__ void __launch_bounds__(256) k_gemm(const float* __restrict__ bf_,
                                              const float* __restrict__ bb_) {
    extern __shared__ char sm[];
    int tid = threadIdx.x, lane = tid & 31, w = tid >> 5;
    int m0 = blockIdx.x * 128;
    int n0 = blockIdx.y * 128;
    int dir = n0 >> 10, nloc = n0 & 1023;

    // stage A tile 128 x 256 bf16 (pitch 528B -> conflict-free ldmatrix)
    for (int i = tid; i < 4096; i += 256) {
        int r = i >> 5, c = i & 31;
        ((uint4*)(sm + r * 528))[c] = ((const uint4*)(d_xb + (size_t)(m0 + r) * 256))[c];
    }
    __syncthreads();

    const uint4* Bp = d_wih2 + ((size_t)dir * 64 + (nloc >> 4)) * 512 + lane;
    float c[16][4];
#pragma unroll
    for (int t = 0; t < 16; t++)
#pragma unroll
        for (int r = 0; r < 4; r++) c[t][r] = 0.f;

    unsigned ab = smem_u32(sm) + (unsigned)(w * 16 + (lane & 15)) * 528 + ((unsigned)(lane >> 4) << 4);
#pragma unroll
    for (int kt = 0; kt < 16; kt++) {
        unsigned a[4];
        LDSM4(a, ab + (unsigned)kt * 32);
#pragma unroll
        for (int p = 0; p < 8; p++) {
            uint4 bq = Bp[p * 512 + kt * 32];
            MMA_BF16(c[2 * p], a, bq.x, bq.y);
            MMA_BF16(c[2 * p + 1], a, bq.z, bq.w);
        }
    }
    const float* Bv = dir ? bb_ : bf_;
    int mrow = m0 + w * 16 + (lane >> 2);
    float* gbase = d_gx + ((size_t)dir * 65536 + mrow) * 1024 + nloc + (lane & 3) * 2;
#pragma unroll
    for (int nt = 0; nt < 16; nt++) {
        float2 bv = *(const float2*)(Bv + nloc + nt * 8 + (lane & 3) * 2);
        *(float2*)(gbase + nt * 8) = make_float2(c[nt][0] + bv.x, c[nt][1] + bv.y);
        *(float2*)(gbase + 8 * 1024 + nt * 8) = make_float2(c[nt][2] + bv.x, c[nt][3] + bv.y);
    }
}

// ---------------- K2: LSTM recurrence, cluster-of-4, single sync phase ----------------
#define HPITCH   528
#define HBUFB    8448
#define OFF_H    131072
#define OFF_RECV 147968
#define RECVB    16384
#define OFF_MBAR 180736
#define SMEM_R   180752

__global__ void __launch_bounds__(512, 1) __cluster_dims__(4, 1, 1) k_recur() {
    extern __shared__ char sm[];
    int tid = threadIdx.x;
    unsigned rank;
    asm("mov.u32 %0, %%cluster_ctarank;" : "=r"(rank));
    int cid = blockIdx.x >> 2;
    int dir = cid >> 4;
    int b0 = (cid & 15) * 8;
    int lane = tid & 31, w = tid >> 5;

    // this gate's weights (128 KB) into smem once
    const uint4* wg = d_whh2 + (size_t)(dir * 4 + (int)rank) * 8192;
    uint4* smW = (uint4*)sm;
    for (int i = tid; i < 8192; i += 512) smW[i] = wg[i];
    for (int i = tid; i < 2 * HBUFB / 4; i += 512) ((unsigned*)(sm + OFF_H))[i] = 0u;

    ull* mbar = (ull*)(sm + OFF_MBAR);
    if (tid == 0)
        asm volatile("mbarrier.init.shared.b64 [%0], 4;" :: "r"(smem_u32(mbar)) : "memory");
    __syncthreads();
    asm volatile("barrier.cluster.arrive.aligned;" ::: "memory");
    asm volatile("barrier.cluster.wait.aligned;" ::: "memory");

    unsigned b_l  = smem_u32(mbar);
    unsigned rv_l = smem_u32(sm + OFF_RECV);
    unsigned h_l  = smem_u32(sm + OFF_H);
    unsigned rb[4], rrv[4];
#pragma unroll
    for (int r = 0; r < 4; r++) { rb[r] = mapa_u32(b_l, r); rrv[r] = mapa_u32(rv_l, r); }

    // producer roles
    int bE = lane >> 2, li = lane & 3, nl = w * 16 + li * 2;
    unsigned soff = (unsigned)((int)rank * 8 + bE) * 512 + (unsigned)w * 32 + (unsigned)li * 8;
    const uint4* Wme = smW + w * 512 + lane;
    unsigned abase0 = h_l + (unsigned)(lane & 15) * HPITCH + ((unsigned)(lane >> 4) << 4);

    // consumer roles (redundant cell update across CTAs)
    int jp = tid & 127, bq2 = tid >> 7;
    unsigned woff = ((unsigned)(jp >> 3) << 5) + ((unsigned)(jp & 3) << 3) + (((unsigned)(jp >> 2) & 1u) << 2);

    float cc[2][2] = {{0.f, 0.f}, {0.f, 0.f}};
    const float* gxb = d_gx + (size_t)dir * 65536 * 1024;
    int buf = 0;

    int l0 = dir ? 511 : 0;
    const float* gxp = gxb + (size_t)(l0 * 128 + b0 + bE) * 1024 + (int)rank * 256 + nl;
    float2 ga = *(const float2*)gxp;
    float2 gb2 = *(const float2*)(gxp + 8);

    for (int step = 0; step < 512; step++) {
        int l = dir ? (511 - step) : step;

        // matvec: gate preacts for 8 batch rows (M=16 tile, rows 8-15 pad)
        float c0[4] = {0.f, 0.f, 0.f, 0.f}, c1[4] = {0.f, 0.f, 0.f, 0.f};
        unsigned ab = abase0 + (unsigned)buf * HBUFB;
#pragma unroll
        for (int kt = 0; kt < 16; kt++) {
            unsigned a[4];
            LDSM4(a, ab + (unsigned)kt * 32);
            uint4 bq = Wme[kt * 32];
            MMA_BF16(c0, a, bq.x, bq.y);
            MMA_BF16(c1, a, bq.z, bq.w);
        }
        // add own gx slice, multicast complete preacts to all 4 CTAs
        unsigned u0 = cvt_bf2(c0[1] + ga.y, c0[0] + ga.x);
        unsigned u1 = cvt_bf2(c1[1] + gb2.y, c1[0] + gb2.x);
        unsigned bsel = (unsigned)(step & 1) * RECVB;
#pragma unroll
        for (int r = 0; r < 4; r++) {
            unsigned ad = rrv[r] + bsel + soff;
            asm volatile("st.shared::cluster.u32 [%0],%1;" :: "r"(ad), "r"(u0) : "memory");
            asm volatile("st.shared::cluster.u32 [%0],%1;" :: "r"(ad + 4), "r"(u1) : "memory");
        }
        __syncthreads();
        if (tid == 0) {
#pragma unroll
            for (int r = 0; r < 4; r++)
                asm volatile("mbarrier.arrive.release.cluster.shared::cluster.b64 _, [%0];"
                             :: "r"(rb[r]) : "memory");
        }
        // prefetch next step's gx into the wait shadow
        if (step < 511) {
            int ln = dir ? (510 - step) : (step + 1);
            gxp = gxb + (size_t)(ln * 128 + b0 + bE) * 1024 + (int)rank * 256 + nl;
            ga = *(const float2*)gxp;
            gb2 = *(const float2*)(gxp + 8);
        }
        {
            unsigned ph = (unsigned)step & 1u, done;
            asm volatile("{\n\t.reg .pred p;\n\t"
                         "mbarrier.try_wait.parity.acquire.cluster.shared::cta.b64 p, [%1], %2;\n\t"
                         "selp.b32 %0, 1, 0, p;\n\t}"
                         : "=r"(done) : "r"(b_l), "r"(ph) : "memory");
            while (!done)
                asm volatile("{\n\t.reg .pred p;\n\t"
                             "mbarrier.try_wait.parity.acquire.cluster.shared::cta.b64 p, [%1], %2, 0x989680;\n\t"
                             "selp.b32 %0, 1, 0, p;\n\t}"
                             : "=r"(done) : "r"(b_l), "r"(ph) : "memory");
        }

        // cell update: all 8 rows computed on every CTA (h stays local)
        const char* rbp = sm + OFF_RECV + bsel;
#pragma unroll
        for (int q = 0; q < 2; q++) {
            int b = bq2 * 2 + q;
            unsigned iu = *(const unsigned*)(rbp + (b)      * 512 + woff);
            unsigned fu = *(const unsigned*)(rbp + (b + 8)  * 512 + woff);
            unsigned gu = *(const unsigned*)(rbp + (b + 16) * 512 + woff);
            unsigned ou = *(const unsigned*)(rbp + (b + 24) * 512 + woff);
            float i0 = sigt(bflo(iu)), f0 = sigt(bflo(fu)), g0 = tanhe(bflo(gu)), o0 = sigt(bflo(ou));
            float i1 = sigt(bfhi(iu)), f1 = sigt(bfhi(fu)), g1 = tanhe(bfhi(gu)), o1 = sigt(bfhi(ou));
            cc[q][0] = f0 * cc[q][0] + i0 * g0;
            cc[q][1] = f1 * cc[q][1] + i1 * g1;
            float hv0 = o0 * tanhe(cc[q][0]);
            float hv1 = o1 * tanhe(cc[q][1]);
            *(unsigned*)(sm + OFF_H + (buf ^ 1) * HBUFB + b * HPITCH + jp * 4) = cvt_bf2(hv1, hv0);
            if (bq2 == (int)rank)
                *(float2*)(d_hcat + ((size_t)(b0 + b) * 512 + l) * 512 + dir * 256 + 2 * jp) =
                    make_float2(hv0, hv1);
        }
        __syncthreads();
        buf ^= 1;
    }

    asm volatile("barrier.cluster.arrive.aligned;" ::: "memory");
    asm volatile("barrier.cluster.wait.aligned;" ::: "memory");
}

// ---------------- K3: emission = hcat @ w_cls^T + b_cls ----------------
__global__ void __launch_bounds__(256) k_emis(const float* __restrict__ wcls,
                                              const float* __restrict__ bcls) {
    __shared__ float wc[16 * 512];
    int tid = threadIdx.x;
    for (int i = tid; i < 16 * 512 / 4; i += 256)
        ((float4*)wc)[i] = ((const float4*)wcls)[i];
    __syncthreads();
    int m = blockIdx.x * 8 + (tid >> 5);
    int lane = tid & 31;
    float acc[16];
#pragma unroll
    for (int t = 0; t < 16; t++) acc[t] = 0.f;
    const float* hp = d_hcat + (size_t)m * 512;
#pragma unroll
    for (int it = 0; it < 4; it++) {
        int k = it * 128 + lane * 4;
        float4 h4 = *(const float4*)(hp + k);
#pragma unroll
        for (int t = 0; t < 16; t++) {
            float4 w4 = *(const float4*)(wc + t * 512 + k);
            acc[t] += h4.x * w4.x + h4.y * w4.y + h4.z * w4.z + h4.w * w4.w;
        }
    }
#pragma unroll
    for (int t = 0; t < 16; t++)
#pragma unroll
        for (int off = 16; off; off >>= 1) acc[t] += __shfl_xor_sync(0xffffffffu, acc[t], off);
    if (lane < 16) {
        float v = acc[0];
#pragma unroll
        for (int t = 1; t < 16; t++) v = (lane == t) ? acc[t] : v;
        d_emission[(size_t)m * 16 + lane] = v + bcls[lane];
    }
}

// ---------------- K4: CRF golden + forward (1 warp / batch row) ----------------
__global__ void k_crf(const int* __restrict__ tag, const float* __restrict__ trans) {
    __shared__ float tr[256];
    int b = blockIdx.x, lane = threadIdx.x;
    for (int i = lane; i < 256; i += 32) tr[i] = trans[i];
    __syncwarp();
    int cur = lane & 15;
    float tcol[16];
#pragma unroll
    for (int p = 0; p < 16; p++) tcol[p] = tr[p * 16 + cur];
    const int* tg = tag + b * 512;
    int len = 0;
    for (int l2 = lane; l2 < 512; l2 += 32) len += (tg[l2] != 0);
#pragma unroll
    for (int off = 16; off; off >>= 1) len += __shfl_xor_sync(0xffffffffu, len, off);

    const float* em = d_emission + (size_t)b * 512 * 16;
    float gsum = 0.f;
    for (int l2 = lane; l2 < 512; l2 += 32)
        if (l2 < len) {
            int t = tg[l2];
            int pv = l2 ? tg[l2 - 1] : 14;       // START=14
            gsum += em[l2 * 16 + t] + tr[pv * 16 + t];
        }
#pragma unroll
    for (int off = 16; off; off >>= 1) gsum += __shfl_xor_sync(0xffffffffu, gsum, off);

    float score = em[cur] + tr[14 * 16 + cur];
    for (int t = 1; t < 512; t++) {
        float v[16];
#pragma unroll
        for (int p = 0; p < 16; p++)
            v[p] = __shfl_sync(0xffffffffu, score, p) + tcol[p];
        float m0 = fmaxf(fmaxf(v[0], v[1]), fmaxf(v[2], v[3]));
        float m1 = fmaxf(fmaxf(v[4], v[5]), fmaxf(v[6], v[7]));
        float m2 = fmaxf(fmaxf(v[8], v[9]), fmaxf(v[10], v[11]));
        float m3 = fmaxf(fmaxf(v[12], v[13]), fmaxf(v[14], v[15]));
        float m = fmaxf(fmaxf(m0, m1), fmaxf(m2, m3));
        float e[16];
#pragma unroll
        for (int p = 0; p < 16; p++) e[p] = __expf(v[p] - m);
        float s0 = (e[0] + e[1]) + (e[2] + e[3]);
        float s1 = (e[4] + e[5]) + (e[6] + e[7]);
        float s2 = (e[8] + e[9]) + (e[10] + e[11]);
        float s3 = (e[12] + e[13]) + (e[14] + e[15]);
        float s = (s0 + s1) + (s2 + s3);
        float ns = em[t * 16 + cur] + m + __logf(s);
        score = (t < len) ? ns : score;
    }
    if (lane == 15) atomicAdd(&d_acc[0], (double)score);  // END=15
    if (lane == 0)  atomicAdd(&d_acc[1], (double)gsum);
}

__global__ void k_final(float* out) {
    out[0] = (float)((d_acc[0] - d_acc[1]) / 128.0);
}

// ---------------- launch ----------------
extern "C" void kernel_launch(void* const* d_in, const int* in_sizes, int n_in,
                              void* d_out, int out_size) {
    const int*   batch_data = (const int*)d_in[0];
    const int*   batch_tag  = (const int*)d_in[1];
    const float* emb        = (const float*)d_in[2];
    const float* w_ih_f     = (const float*)d_in[3];
    const float* w_hh_f     = (const float*)d_in[4];
    const float* b_f        = (const float*)d_in[5];
    const float* w_ih_b     = (const float*)d_in[6];
    const float* w_hh_b     = (const float*)d_in[7];
    const float* b_b        = (const float*)d_in[8];
    const float* w_cls      = (const float*)d_in[9];
    const float* b_cls      = (const float*)d_in[10];
    const float* transition = (const float*)d_in[11];

    cudaFuncSetAttribute(k_recur, cudaFuncAttributeMaxDynamicSharedMemorySize, SMEM_R);
    cudaFuncSetAttribute(k_gemm, cudaFuncAttributeMaxDynamicSharedMemorySize, GSM);

    k_prep<<<512, 256>>>(w_hh_f, w_hh_b, w_ih_f, w_ih_b);
    k_gather<<<8192, 256>>>(batch_data, emb);
    k_gemm<<<dim3(512, 16), 256, GSM>>>(b_f, b_b);
    k_recur<<<128, 512, SMEM_R>>>();
    k_emis<<<8192, 256>>>(w_cls, b_cls);
    k_crf<<<128, 32>>>(batch_tag, transition);
    k_final<<<1, 1>>>((float*)d_out);
}

// round 8
// speedup vs baseline: 5.0176x; 1.1832x over previous
#include <cuda_runtime.h>
#include <cuda_bf16.h>

typedef unsigned long long ull;

// ---------------- device scratch (no runtime allocation) ----------------
__device__ __nv_bfloat16 d_xb[(size_t)65536 * 256];  // gathered embeddings bf16 [m][256]
__device__ float d_gx[(size_t)2 * 65536 * 1024];     // input gate preacts [dir][m][1024]
__device__ float d_hcat[(size_t)128 * 512 * 512];    // [b][l][hf|hb]
__device__ float d_emission[(size_t)65536 * 16];     // [b*512+l][16]
__device__ uint4 d_whh2[65536];                      // W_hh mma B fragments [dir][gate][w][kt][lane]
__device__ uint4 d_wih2[65536];                      // W_ih mma B fragments [dir][nt16][kt][lane]
__device__ double d_acc[2];                          // [all_path, golden]

// ---------------- helpers ----------------
__device__ __forceinline__ float bflo(unsigned w) { return __uint_as_float(w << 16); }
__device__ __forceinline__ float bfhi(unsigned w) { return __uint_as_float(w & 0xffff0000u); }
__device__ __forceinline__ float bfhalf(unsigned u, int hi) {
    return __uint_as_float(hi ? (u & 0xffff0000u) : (u << 16));
}
__device__ __forceinline__ float tanha(float x) {
    float r; asm("tanh.approx.f32 %0,%1;" : "=f"(r) : "f"(x)); return r;
}
__device__ __forceinline__ float sigt(float x) { return fmaf(tanha(0.5f * x), 0.5f, 0.5f); }

__device__ __forceinline__ unsigned smem_u32(const void* p) {
    unsigned a;
    asm("{ .reg .u64 t; cvta.to.shared.u64 t, %1; cvt.u32.u64 %0, t; }" : "=r"(a) : "l"(p));
    return a;
}
__device__ __forceinline__ unsigned mapa_u32(unsigned a, unsigned rank) {
    unsigned d; asm("mapa.shared::cluster.u32 %0,%1,%2;" : "=r"(d) : "r"(a), "r"(rank));
    return d;
}
__device__ __forceinline__ unsigned cvt_bf2(float hi, float lo) {
    unsigned u; asm("cvt.rn.bf16x2.f32 %0,%1,%2;" : "=r"(u) : "f"(hi), "f"(lo)); return u;
}

#define MMA_BF16(C, A, B0, B1)                                                          \
    asm volatile("mma.sync.aligned.m16n8k16.row.col.f32.bf16.bf16.f32 "                 \
                 "{%0,%1,%2,%3},{%4,%5,%6,%7},{%8,%9},{%0,%1,%2,%3};"                   \
                 : "+f"((C)[0]), "+f"((C)[1]), "+f"((C)[2]), "+f"((C)[3])               \
                 : "r"((A)[0]), "r"((A)[1]), "r"((A)[2]), "r"((A)[3]),                  \
                   "r"(B0), "r"(B1))
#define LDSM4(R, ADDR)                                                                  \
    asm volatile("ldmatrix.sync.aligned.m8n8.x4.shared.b16 {%0,%1,%2,%3},[%4];"         \
                 : "=r"((R)[0]), "=r"((R)[1]), "=r"((R)[2]), "=r"((R)[3]) : "r"(ADDR))

#define MBAR_WAIT(ADDR, PH)                                                             \
    do {                                                                                \
        unsigned done;                                                                  \
        asm volatile("{\n\t.reg .pred p;\n\t"                                           \
                     "mbarrier.try_wait.parity.acquire.cluster.shared::cta.b64 p, [%1], %2;\n\t" \
                     "selp.b32 %0, 1, 0, p;\n\t}"                                       \
                     : "=r"(done) : "r"(ADDR), "r"(PH) : "memory");                     \
        while (!done)                                                                   \
            asm volatile("{\n\t.reg .pred p;\n\t"                                       \
                         "mbarrier.try_wait.parity.acquire.cluster.shared::cta.b64 p, [%1], %2, 0x989680;\n\t" \
                         "selp.b32 %0, 1, 0, p;\n\t}"                                   \
                         : "=r"(done) : "r"(ADDR), "r"(PH) : "memory");                 \
    } while (0)

// ---------------- K0: prep (whh + wih fragments, zero acc) ----------------
__device__ __forceinline__ unsigned pkbf(const float* s, int n, int k) {
    unsigned short lo = __bfloat16_as_ushort(__float2bfloat16(s[n * 256 + k]));
    unsigned short hi = __bfloat16_as_ushort(__float2bfloat16(s[n * 256 + k + 1]));
    return ((unsigned)hi << 16) | (unsigned)lo;
}
__global__ void k_prep(const float* __restrict__ whf, const float* __restrict__ whb,
                       const float* __restrict__ wif, const float* __restrict__ wib) {
    int e = blockIdx.x * 256 + threadIdx.x;   // 0..131071
    if (e < 65536) {
        int lane = e & 31, kt = (e >> 5) & 15, w = (e >> 9) & 15;
        int g = (e >> 13) & 3, dir = (e >> 15) & 1;
        const float* src = dir ? whb : whf;
        int row = g * 256 + w * 16 + (lane >> 2);
        int k0 = kt * 16 + (lane & 3) * 2;
        uint4 v;
        v.x = pkbf(src, row, k0);     v.y = pkbf(src, row, k0 + 8);
        v.z = pkbf(src, row + 8, k0); v.w = pkbf(src, row + 8, k0 + 8);
        d_whh2[e] = v;
    } else {
        int f = e - 65536;
        int lane = f & 31, kt = (f >> 5) & 15, nt = (f >> 9) & 63, dir = (f >> 15) & 1;
        const float* src = dir ? wib : wif;
        int row = nt * 16 + (lane >> 2);
        int k0 = kt * 16 + (lane & 3) * 2;
        uint4 v;
        v.x = pkbf(src, row, k0);     v.y = pkbf(src, row, k0 + 8);
        v.z = pkbf(src, row + 8, k0); v.w = pkbf(src, row + 8, k0 + 8);
        d_wih2[f] = v;
    }
    if (e < 2) d_acc[e] = 0.0;
}

// ---------------- K1a: embedding gather (fp32 -> bf16) ----------------
__global__ void k_gather(const int* __restrict__ bd, const float* __restrict__ emb) {
    int m = blockIdx.x * 8 + (threadIdx.x >> 5);
    int lane = threadIdx.x & 31;
    int b = m & 127, l = m >> 7;
    int idx = bd[b * 512 + l];
    const float* src = emb + (size_t)idx * 256;
    unsigned* dst = (unsigned*)(d_xb + (size_t)m * 256);
#pragma unroll
    for (int t = 0; t < 4; t++) {
        int i = lane + t * 32;
        float2 v = *(const float2*)(src + 2 * i);
        dst[i] = cvt_bf2(v.y, v.x);
    }
}

// ---------------- K1b: input projection via mma.sync bf16 ----------------
#define GSM 67584
__global__ void __launch_bounds__(256) k_gemm(const float* __restrict__ bf_,
                                              const float* __restrict__ bb_) {
    extern __shared__ char sm[];
    int tid = threadIdx.x, lane = tid & 31, w = tid >> 5;
    int m0 = blockIdx.x * 128;
    int n0 = blockIdx.y * 128;
    int dir = n0 >> 10, nloc = n0 & 1023;

    for (int i = tid; i < 4096; i += 256) {
        int r = i >> 5, c = i & 31;
        ((uint4*)(sm + r * 528))[c] = ((const uint4*)(d_xb + (size_t)(m0 + r) * 256))[c];
    }
    __syncthreads();

    const uint4* Bp = d_wih2 + ((size_t)dir * 64 + (nloc >> 4)) * 512 + lane;
    float c[16][4];
#pragma unroll
    for (int t = 0; t < 16; t++)
#pragma unroll
        for (int r = 0; r < 4; r++) c[t][r] = 0.f;

    unsigned ab = smem_u32(sm) + (unsigned)(w * 16 + (lane & 15)) * 528 + ((unsigned)(lane >> 4) << 4);
#pragma unroll
    for (int kt = 0; kt < 16; kt++) {
        unsigned a[4];
        LDSM4(a, ab + (unsigned)kt * 32);
#pragma unroll
        for (int p = 0; p < 8; p++) {
            uint4 bq = Bp[p * 512 + kt * 32];
            MMA_BF16(c[2 * p], a, bq.x, bq.y);
            MMA_BF16(c[2 * p + 1], a, bq.z, bq.w);
        }
    }
    const float* Bv = dir ? bb_ : bf_;
    int mrow = m0 + w * 16 + (lane >> 2);
    float* gbase = d_gx + ((size_t)dir * 65536 + mrow) * 1024 + nloc + (lane & 3) * 2;
#pragma unroll
    for (int nt = 0; nt < 16; nt++) {
        float2 bv = *(const float2*)(Bv + nloc + nt * 8 + (lane & 3) * 2);
        *(float2*)(gbase + nt * 8) = make_float2(c[nt][0] + bv.x, c[nt][1] + bv.y);
        *(float2*)(gbase + 8 * 1024 + nt * 8) = make_float2(c[nt][2] + bv.x, c[nt][3] + bv.y);
    }
}

// ---------------- K2: LSTM recurrence, cluster-of-4 gate-split, two-phase ----------------
#define HPITCH   528
#define HBUFB    8448
#define OFF_H    131072
#define OFF_RECV 147968                  // 4 KB: [gate][q][128 pairs]
#define OFF_MBAR 152064
#define SMEM_R   152080

__global__ void __launch_bounds__(512, 1) __cluster_dims__(4, 1, 1) k_recur() {
    extern __shared__ char sm[];
    int tid = threadIdx.x;
    unsigned rank;
    asm("mov.u32 %0, %%cluster_ctarank;" : "=r"(rank));
    int cid = blockIdx.x >> 2;
    int dir = cid >> 4;
    int b0 = (cid & 15) * 8;
    int lane = tid & 31, w = tid >> 5;

    // this gate's weights (128 KB) into smem once
    const uint4* wg = d_whh2 + (size_t)(dir * 4 + (int)rank) * 8192;
    uint4* smW = (uint4*)sm;
    for (int i = tid; i < 8192; i += 512) smW[i] = wg[i];
    for (int i = tid; i < 2 * HBUFB / 4; i += 512) ((unsigned*)(sm + OFF_H))[i] = 0u;

    ull* mbar = (ull*)(sm + OFF_MBAR);
    if (tid == 0) {
        asm volatile("mbarrier.init.shared.b64 [%0], 3;" :: "r"(smem_u32(&mbar[0])) : "memory");
        asm volatile("mbarrier.init.shared.b64 [%0], 3;" :: "r"(smem_u32(&mbar[1])) : "memory");
    }
    __syncthreads();
    asm volatile("barrier.cluster.arrive.aligned;" ::: "memory");
    asm volatile("barrier.cluster.wait.aligned;" ::: "memory");

    unsigned rv_l = smem_u32(sm + OFF_RECV);
    unsigned h_l  = smem_u32(sm + OFF_H);
    unsigned b1_l = smem_u32(&mbar[0]);
    unsigned b2_l = smem_u32(&mbar[1]);
    unsigned rh[4], rb1[4], rb2[4];
#pragma unroll
    for (int r = 0; r < 4; r++) {
        rh[r]  = mapa_u32(h_l, r);
        rb1[r] = mapa_u32(b1_l, r);
        rb2[r] = mapa_u32(b2_l, r);
    }

    // producer roles: this CTA computes gate `rank` for 8 batch rows
    unsigned abase0 = h_l + (unsigned)(lane & 15) * HPITCH + ((unsigned)(lane >> 4) << 4);
    int bE = lane >> 2;
    unsigned rdst = (unsigned)(bE >> 1);
    int qE = bE & 1;
    int nl = w * 16 + (lane & 3) * 2;
    unsigned dst0 = mapa_u32(rv_l, rdst) + ((unsigned)rank * 256 + qE * 128 + (nl >> 1)) * 4;
    const uint4* Wme = smW + w * 512 + lane;

    // consumer roles: cell update for own 2 batch rows
    int q = tid >> 8, j = tid & 255;
    int b_own = b0 + (int)rank * 2 + q;
    int hrow = (int)rank * 2 + q;
    const unsigned* rcv = (const unsigned*)(sm + OFF_RECV) + q * 128 + (j >> 1);
    int hlf = j & 1;

    float cc = 0.f;
    const float* gxb = d_gx + (size_t)dir * 65536 * 1024;
    int buf = 0;

    // producer gx prefetch (gate `rank` slice for batch bE)
    int l0 = dir ? 511 : 0;
    const float* gxp = gxb + (size_t)(l0 * 128 + b0 + bE) * 1024 + (int)rank * 256 + nl;
    float2 ga = *(const float2*)gxp;
    float2 gb2 = *(const float2*)(gxp + 8);

    for (int step = 0; step < 512; step++) {
        int l = dir ? (511 - step) : step;

        // ---- matvec: this gate's 256 preacts for 8 batches ----
        float c0[4] = {0.f, 0.f, 0.f, 0.f}, c1[4] = {0.f, 0.f, 0.f, 0.f};
        unsigned ab = abase0 + (unsigned)buf * HBUFB;
#pragma unroll
        for (int kt = 0; kt < 16; kt++) {
            unsigned a[4];
            LDSM4(a, ab + (unsigned)kt * 32);
            uint4 bq = Wme[kt * 32];
            MMA_BF16(c0, a, bq.x, bq.y);
            MMA_BF16(c1, a, bq.z, bq.w);
        }
        // ship complete preacts (matvec + gx) to owner CTA
        unsigned u0 = cvt_bf2(c0[1] + ga.y, c0[0] + ga.x);
        unsigned u1 = cvt_bf2(c1[1] + gb2.y, c1[0] + gb2.x);
        asm volatile("st.shared::cluster.u32 [%0],%1;" :: "r"(dst0), "r"(u0) : "memory");
        asm volatile("st.shared::cluster.u32 [%0],%1;" :: "r"(dst0 + 16), "r"(u1) : "memory");
        __syncthreads();
        if (tid == 0) {
#pragma unroll
            for (int r = 0; r < 4; r++)
                if (r != (int)rank)
                    asm volatile("mbarrier.arrive.release.cluster.shared::cluster.b64 _, [%0];"
                                 :: "r"(rb1[r]) : "memory");
        }
        {
            unsigned ph = (unsigned)step & 1u;
            MBAR_WAIT(b1_l, ph);
        }

        // ---- cell update for own 2 batch rows (preacts already include gx) ----
        float pi = bfhalf(rcv[0],   hlf);
        float pf = bfhalf(rcv[256], hlf);
        float pg = bfhalf(rcv[512], hlf);
        float po = bfhalf(rcv[768], hlf);
        float i_ = sigt(pi), f_ = sigt(pf), g_ = tanha(pg), o_ = sigt(po);
        cc = f_ * cc + i_ * g_;
        float hv = o_ * tanha(cc);

        // ---- broadcast new h row to all 4 CTAs + paired hcat store ----
        float hn = __shfl_down_sync(0xffffffffu, hv, 1);
        if (!hlf) {
            unsigned hu = cvt_bf2(hn, hv);
            unsigned off = (unsigned)(buf ^ 1) * HBUFB + (unsigned)hrow * HPITCH + (unsigned)j * 2;
#pragma unroll
            for (int r = 0; r < 4; r++)
                asm volatile("st.shared::cluster.u32 [%0],%1;" :: "r"(rh[r] + off), "r"(hu) : "memory");
            *(float2*)(d_hcat + ((size_t)b_own * 512 + l) * 512 + dir * 256 + j) =
                make_float2(hv, hn);
        }
        __syncthreads();
        if (tid == 0) {
#pragma unroll
            for (int r = 0; r < 4; r++)
                if (r != (int)rank)
                    asm volatile("mbarrier.arrive.release.cluster.shared::cluster.b64 _, [%0];"
                                 :: "r"(rb2[r]) : "memory");
        }
        // producer gx prefetch for next step (into wait-2 shadow)
        if (step < 511) {
            int ln = dir ? (510 - step) : (step + 1);
            gxp = gxb + (size_t)(ln * 128 + b0 + bE) * 1024 + (int)rank * 256 + nl;
            ga = *(const float2*)gxp;
            gb2 = *(const float2*)(gxp + 8);
        }
        {
            unsigned ph = (unsigned)step & 1u;
            MBAR_WAIT(b2_l, ph);
        }
        buf ^= 1;
    }

    asm volatile("barrier.cluster.arrive.aligned;" ::: "memory");
    asm volatile("barrier.cluster.wait.aligned;" ::: "memory");
}

// ---------------- K3: emission = hcat @ w_cls^T + b_cls ----------------
__global__ void __launch_bounds__(256) k_emis(const float* __restrict__ wcls,
                                              const float* __restrict__ bcls) {
    __shared__ float wc[16 * 512];
    int tid = threadIdx.x;
    for (int i = tid; i < 16 * 512 / 4; i += 256)
        ((float4*)wc)[i] = ((const float4*)wcls)[i];
    __syncthreads();
    int m = blockIdx.x * 8 + (tid >> 5);
    int lane = tid & 31;
    float acc[16];
#pragma unroll
    for (int t = 0; t < 16; t++) acc[t] = 0.f;
    const float* hp = d_hcat + (size_t)m * 512;
#pragma unroll
    for (int it = 0; it < 4; it++) {
        int k = it * 128 + lane * 4;
        float4 h4 = *(const float4*)(hp + k);
#pragma unroll
        for (int t = 0; t < 16; t++) {
            float4 w4 = *(const float4*)(wc + t * 512 + k);
            acc[t] += h4.x * w4.x + h4.y * w4.y + h4.z * w4.z + h4.w * w4.w;
        }
    }
#pragma unroll
    for (int t = 0; t < 16; t++)
#pragma unroll
        for (int off = 16; off; off >>= 1) acc[t] += __shfl_xor_sync(0xffffffffu, acc[t], off);
    if (lane < 16) {
        float v = acc[0];
#pragma unroll
        for (int t = 1; t < 16; t++) v = (lane == t) ? acc[t] : v;
        d_emission[(size_t)m * 16 + lane] = v + bcls[lane];
    }
}

// ---------------- K4: CRF golden + forward (1 warp / batch row) ----------------
__global__ void k_crf(const int* __restrict__ tag, const float* __restrict__ trans) {
    __shared__ float tr[256];
    int b = blockIdx.x, lane = threadIdx.x;
    for (int i = lane; i < 256; i += 32) tr[i] = trans[i];
    __syncwarp();
    int cur = lane & 15;
    float tcol[16];
#pragma unroll
    for (int p = 0; p < 16; p++) tcol[p] = tr[p * 16 + cur];
    const int* tg = tag + b * 512;
    int len = 0;
    for (int l2 = lane; l2 < 512; l2 += 32) len += (tg[l2] != 0);
#pragma unroll
    for (int off = 16; off; off >>= 1) len += __shfl_xor_sync(0xffffffffu, len, off);

    const float* em = d_emission + (size_t)b * 512 * 16;
    float gsum = 0.f;
    for (int l2 = lane; l2 < 512; l2 += 32)
        if (l2 < len) {
            int t = tg[l2];
            int pv = l2 ? tg[l2 - 1] : 14;       // START=14
            gsum += em[l2 * 16 + t] + tr[pv * 16 + t];
        }
#pragma unroll
    for (int off = 16; off; off >>= 1) gsum += __shfl_xor_sync(0xffffffffu, gsum, off);

    float score = em[cur] + tr[14 * 16 + cur];
    for (int t = 1; t < 512; t++) {
        float v[16];
#pragma unroll
        for (int p = 0; p < 16; p++)
            v[p] = __shfl_sync(0xffffffffu, score, p) + tcol[p];
        float m0 = fmaxf(fmaxf(v[0], v[1]), fmaxf(v[2], v[3]));
        float m1 = fmaxf(fmaxf(v[4], v[5]), fmaxf(v[6], v[7]));
        float m2 = fmaxf(fmaxf(v[8], v[9]), fmaxf(v[10], v[11]));
        float m3 = fmaxf(fmaxf(v[12], v[13]), fmaxf(v[14], v[15]));
        float m = fmaxf(fmaxf(m0, m1), fmaxf(m2, m3));
        float e[16];
#pragma unroll
        for (int p = 0; p < 16; p++) e[p] = __expf(v[p] - m);
        float s0 = (e[0] + e[1]) + (e[2] + e[3]);
        float s1 = (e[4] + e[5]) + (e[6] + e[7]);
        float s2 = (e[8] + e[9]) + (e[10] + e[11]);
        float s3 = (e[12] + e[13]) + (e[14] + e[15]);
        float s = (s0 + s1) + (s2 + s3);
        float ns = em[t * 16 + cur] + m + __logf(s);
        score = (t < len) ? ns : score;
    }
    if (lane == 15) atomicAdd(&d_acc[0], (double)score);  // END=15
    if (lane == 0)  atomicAdd(&d_acc[1], (double)gsum);
}

__global__ void k_final(float* out) {
    out[0] = (float)((d_acc[0] - d_acc[1]) / 128.0);
}

// ---------------- launch ----------------
extern "C" void kernel_launch(void* const* d_in, const int* in_sizes, int n_in,
                              void* d_out, int out_size) {
    const int*   batch_data = (const int*)d_in[0];
    const int*   batch_tag  = (const int*)d_in[1];
    const float* emb        = (const float*)d_in[2];
    const float* w_ih_f     = (const float*)d_in[3];
    const float* w_hh_f     = (const float*)d_in[4];
    const float* b_f        = (const float*)d_in[5];
    const float* w_ih_b     = (const float*)d_in[6];
    const float* w_hh_b     = (const float*)d_in[7];
    const float* b_b        = (const float*)d_in[8];
    const float* w_cls      = (const float*)d_in[9];
    const float* b_cls      = (const float*)d_in[10];
    const float* transition = (const float*)d_in[11];

    cudaFuncSetAttribute(k_recur, cudaFuncAttributeMaxDynamicSharedMemorySize, SMEM_R);
    cudaFuncSetAttribute(k_gemm, cudaFuncAttributeMaxDynamicSharedMemorySize, GSM);

    k_prep<<<512, 256>>>(w_hh_f, w_hh_b, w_ih_f, w_ih_b);
    k_gather<<<8192, 256>>>(batch_data, emb);
    k_gemm<<<dim3(512, 16), 256, GSM>>>(b_f, b_b);
    k_recur<<<128, 512, SMEM_R>>>();
    k_emis<<<8192, 256>>>(w_cls, b_cls);
    k_crf<<<128, 32>>>(batch_tag, transition);
    k_final<<<1, 1>>>((float*)d_out);
}

// round 9
// speedup vs baseline: 5.7335x; 1.1427x over previous
#include <cuda_runtime.h>
#include <cuda_bf16.h>

typedef unsigned long long ull;

// ---------------- device scratch (no runtime allocation) ----------------
__device__ __nv_bfloat16 d_xb[(size_t)65536 * 256];  // gathered embeddings bf16 [m][256]
__device__ float d_gx[(size_t)2 * 65536 * 1024];     // input gate preacts [dir][m][1024]
__device__ float d_hcat[(size_t)128 * 512 * 512];    // [b][l][hf|hb]
__device__ float d_emission[(size_t)65536 * 16];     // [b*512+l][16]
__device__ uint4 d_whh2[65536];                      // W_hh mma B fragments [dir][gate][w][kt][lane]
__device__ uint4 d_wih2[65536];                      // W_ih mma B fragments [dir][nt16][kt][lane]
__device__ double d_acc[2];                          // [all_path, golden]

// ---------------- helpers ----------------
__device__ __forceinline__ float bfhalf(unsigned u, int hi) {
    return __uint_as_float(hi ? (u & 0xffff0000u) : (u << 16));
}
__device__ __forceinline__ float tanha(float x) {
    float r; asm("tanh.approx.f32 %0,%1;" : "=f"(r) : "f"(x)); return r;
}
__device__ __forceinline__ float sigt(float x) { return fmaf(tanha(0.5f * x), 0.5f, 0.5f); }

__device__ __forceinline__ unsigned smem_u32(const void* p) {
    unsigned a;
    asm("{ .reg .u64 t; cvta.to.shared.u64 t, %1; cvt.u32.u64 %0, t; }" : "=r"(a) : "l"(p));
    return a;
}
__device__ __forceinline__ unsigned mapa_u32(unsigned a, unsigned rank) {
    unsigned d; asm("mapa.shared::cluster.u32 %0,%1,%2;" : "=r"(d) : "r"(a), "r"(rank));
    return d;
}
__device__ __forceinline__ unsigned cvt_bf2(float hi, float lo) {
    unsigned u; asm("cvt.rn.bf16x2.f32 %0,%1,%2;" : "=r"(u) : "f"(hi), "f"(lo)); return u;
}

#define MMA_BF16(C, A, B0, B1)                                                          \
    asm volatile("mma.sync.aligned.m16n8k16.row.col.f32.bf16.bf16.f32 "                 \
                 "{%0,%1,%2,%3},{%4,%5,%6,%7},{%8,%9},{%0,%1,%2,%3};"                   \
                 : "+f"((C)[0]), "+f"((C)[1]), "+f"((C)[2]), "+f"((C)[3])               \
                 : "r"((A)[0]), "r"((A)[1]), "r"((A)[2]), "r"((A)[3]),                  \
                   "r"(B0), "r"(B1))
#define LDSM4(R, ADDR)                                                                  \
    asm volatile("ldmatrix.sync.aligned.m8n8.x4.shared.b16 {%0,%1,%2,%3},[%4];"         \
                 : "=r"((R)[0]), "=r"((R)[1]), "=r"((R)[2]), "=r"((R)[3]) : "r"(ADDR))

#define MBAR_WAIT(ADDR, PH)                                                             \
    do {                                                                                \
        unsigned done;                                                                  \
        asm volatile("{\n\t.reg .pred p;\n\t"                                           \
                     "mbarrier.try_wait.parity.acquire.cluster.shared::cta.b64 p, [%1], %2;\n\t" \
                     "selp.b32 %0, 1, 0, p;\n\t}"                                       \
                     : "=r"(done) : "r"(ADDR), "r"(PH) : "memory");                     \
        while (!done)                                                                   \
            asm volatile("{\n\t.reg .pred p;\n\t"                                       \
                         "mbarrier.try_wait.parity.acquire.cluster.shared::cta.b64 p, [%1], %2, 0x989680;\n\t" \
                         "selp.b32 %0, 1, 0, p;\n\t}"                                   \
                         : "=r"(done) : "r"(ADDR), "r"(PH) : "memory");                 \
    } while (0)

// ---------------- K0: prep (whh + wih fragments, zero acc) ----------------
__device__ __forceinline__ unsigned pkbf(const float* s, int n, int k) {
    unsigned short lo = __bfloat16_as_ushort(__float2bfloat16(s[n * 256 + k]));
    unsigned short hi = __bfloat16_as_ushort(__float2bfloat16(s[n * 256 + k + 1]));
    return ((unsigned)hi << 16) | (unsigned)lo;
}
__global__ void k_prep(const float* __restrict__ whf, const float* __restrict__ whb,
                       const float* __restrict__ wif, const float* __restrict__ wib) {
    int e = blockIdx.x * 256 + threadIdx.x;   // 0..131071
    if (e < 65536) {
        int lane = e & 31, kt = (e >> 5) & 15, w = (e >> 9) & 15;
        int g = (e >> 13) & 3, dir = (e >> 15) & 1;
        const float* src = dir ? whb : whf;
        int row = g * 256 + w * 16 + (lane >> 2);
        int k0 = kt * 16 + (lane & 3) * 2;
        uint4 v;
        v.x = pkbf(src, row, k0);     v.y = pkbf(src, row, k0 + 8);
        v.z = pkbf(src, row + 8, k0); v.w = pkbf(src, row + 8, k0 + 8);
        d_whh2[e] = v;
    } else {
        int f = e - 65536;
        int lane = f & 31, kt = (f >> 5) & 15, nt = (f >> 9) & 63, dir = (f >> 15) & 1;
        const float* src = dir ? wib : wif;
        int row = nt * 16 + (lane >> 2);
        int k0 = kt * 16 + (lane & 3) * 2;
        uint4 v;
        v.x = pkbf(src, row, k0);     v.y = pkbf(src, row, k0 + 8);
        v.z = pkbf(src, row + 8, k0); v.w = pkbf(src, row + 8, k0 + 8);
        d_wih2[f] = v;
    }
    if (e < 2) d_acc[e] = 0.0;
}

// ---------------- K1a: embedding gather (fp32 -> bf16) ----------------
__global__ void k_gather(const int* __restrict__ bd, const float* __restrict__ emb) {
    int m = blockIdx.x * 8 + (threadIdx.x >> 5);
    int lane = threadIdx.x & 31;
    int b = m & 127, l = m >> 7;
    int idx = bd[b * 512 + l];
    const float* src = emb + (size_t)idx * 256;
    unsigned* dst = (unsigned*)(d_xb + (size_t)m * 256);
#pragma unroll
    for (int t = 0; t < 4; t++) {
        int i = lane + t * 32;
        float2 v = *(const float2*)(src + 2 * i);
        dst[i] = cvt_bf2(v.y, v.x);
    }
}

// ---------------- K1b: input projection via mma.sync bf16 ----------------
#define GSM 67584
__global__ void __launch_bounds__(256) k_gemm(const float* __restrict__ bf_,
                                              const float* __restrict__ bb_) {
    extern __shared__ char sm[];
    int tid = threadIdx.x, lane = tid & 31, w = tid >> 5;
    int m0 = blockIdx.x * 128;
    int n0 = blockIdx.y * 128;
    int dir = n0 >> 10, nloc = n0 & 1023;

    for (int i = tid; i < 4096; i += 256) {
        int r = i >> 5, c = i & 31;
        ((uint4*)(sm + r * 528))[c] = ((const uint4*)(d_xb + (size_t)(m0 + r) * 256))[c];
    }
    __syncthreads();

    const uint4* Bp = d_wih2 + ((size_t)dir * 64 + (nloc >> 4)) * 512 + lane;
    float c[16][4];
#pragma unroll
    for (int t = 0; t < 16; t++)
#pragma unroll
        for (int r = 0; r < 4; r++) c[t][r] = 0.f;

    unsigned ab = smem_u32(sm) + (unsigned)(w * 16 + (lane & 15)) * 528 + ((unsigned)(lane >> 4) << 4);
#pragma unroll
    for (int kt = 0; kt < 16; kt++) {
        unsigned a[4];
        LDSM4(a, ab + (unsigned)kt * 32);
#pragma unroll
        for (int p = 0; p < 8; p++) {
            uint4 bq = Bp[p * 512 + kt * 32];
            MMA_BF16(c[2 * p], a, bq.x, bq.y);
            MMA_BF16(c[2 * p + 1], a, bq.z, bq.w);
        }
    }
    const float* Bv = dir ? bb_ : bf_;
    int mrow = m0 + w * 16 + (lane >> 2);
    float* gbase = d_gx + ((size_t)dir * 65536 + mrow) * 1024 + nloc + (lane & 3) * 2;
#pragma unroll
    for (int nt = 0; nt < 16; nt++) {
        float2 bv = *(const float2*)(Bv + nloc + nt * 8 + (lane & 3) * 2);
        *(float2*)(gbase + nt * 8) = make_float2(c[nt][0] + bv.x, c[nt][1] + bv.y);
        *(float2*)(gbase + 8 * 1024 + nt * 8) = make_float2(c[nt][2] + bv.x, c[nt][3] + bv.y);
    }
}

// ---------------- K2: LSTM recurrence, cluster-of-4 gate-split, weights in regs ----------------
#define HPITCH   528
#define HBUFB    8448
#define OFF_H    0                       // h bufs [0, 16896)
#define OFF_RECV 16896                   // 4 KB: [gate][q][128 pairs]
#define OFF_MBAR 20992
#define SMEM_R   21008

__global__ void __launch_bounds__(512, 1) __cluster_dims__(4, 1, 1) k_recur() {
    extern __shared__ char sm[];
    int tid = threadIdx.x;
    unsigned rank;
    asm("mov.u32 %0, %%cluster_ctarank;" : "=r"(rank));
    int cid = blockIdx.x >> 2;
    int dir = cid >> 4;
    int b0 = (cid & 15) * 8;
    int lane = tid & 31, w = tid >> 5;

    // this warp's weight fragments (16 kt x uint4) -> registers, once
    const uint4* wgp = d_whh2 + (size_t)(dir * 4 + (int)rank) * 8192 + w * 512 + lane;
    uint4 wreg[16];
#pragma unroll
    for (int kt = 0; kt < 16; kt++) wreg[kt] = wgp[kt * 32];

    for (int i = tid; i < 2 * HBUFB / 4; i += 512) ((unsigned*)(sm + OFF_H))[i] = 0u;

    ull* mbar = (ull*)(sm + OFF_MBAR);
    if (tid == 0) {
        asm volatile("mbarrier.init.shared.b64 [%0], 3;" :: "r"(smem_u32(&mbar[0])) : "memory");
        asm volatile("mbarrier.init.shared.b64 [%0], 3;" :: "r"(smem_u32(&mbar[1])) : "memory");
    }
    __syncthreads();
    asm volatile("barrier.cluster.arrive.aligned;" ::: "memory");
    asm volatile("barrier.cluster.wait.aligned;" ::: "memory");

    unsigned rv_l = smem_u32(sm + OFF_RECV);
    unsigned h_l  = smem_u32(sm + OFF_H);
    unsigned b1_l = smem_u32(&mbar[0]);
    unsigned b2_l = smem_u32(&mbar[1]);
    unsigned rh[4], rb1[4], rb2[4];
#pragma unroll
    for (int r = 0; r < 4; r++) {
        rh[r]  = mapa_u32(h_l, r);
        rb1[r] = mapa_u32(b1_l, r);
        rb2[r] = mapa_u32(b2_l, r);
    }

    // producer roles: this CTA computes gate `rank` for 8 batch rows
    unsigned abase0 = h_l + (unsigned)(lane & 15) * HPITCH + ((unsigned)(lane >> 4) << 4);
    int bE = lane >> 2;
    unsigned rdst = (unsigned)(bE >> 1);
    int qE = bE & 1;
    int nl = w * 16 + (lane & 3) * 2;
    unsigned dst0 = mapa_u32(rv_l, rdst) + ((unsigned)rank * 256 + qE * 128 + (nl >> 1)) * 4;

    // consumer roles: cell update for own 2 batch rows
    int q = tid >> 8, j = tid & 255;
    int b_own = b0 + (int)rank * 2 + q;
    int hrow = (int)rank * 2 + q;
    const unsigned* rcv = (const unsigned*)(sm + OFF_RECV) + q * 128 + (j >> 1);
    int hlf = j & 1;

    float cc = 0.f;
    const float* gxb = d_gx + (size_t)dir * 65536 * 1024;
    int buf = 0;

    // producer gx prefetch (gate `rank` slice for batch bE)
    int l0 = dir ? 511 : 0;
    const float* gxp = gxb + (size_t)(l0 * 128 + b0 + bE) * 1024 + (int)rank * 256 + nl;
    float2 ga = *(const float2*)gxp;
    float2 gb2 = *(const float2*)(gxp + 8);

    for (int step = 0; step < 512; step++) {
        int l = dir ? (511 - step) : step;

        // ---- matvec: this gate's 256 preacts for 8 batches (weights in regs) ----
        float c0[4] = {0.f, 0.f, 0.f, 0.f}, c1[4] = {0.f, 0.f, 0.f, 0.f};
        unsigned ab = abase0 + (unsigned)buf * HBUFB;
#pragma unroll
        for (int kt = 0; kt < 16; kt++) {
            unsigned a[4];
            LDSM4(a, ab + (unsigned)kt * 32);
            MMA_BF16(c0, a, wreg[kt].x, wreg[kt].y);
            MMA_BF16(c1, a, wreg[kt].z, wreg[kt].w);
        }
        // ship complete preacts (matvec + gx) to owner CTA
        unsigned u0 = cvt_bf2(c0[1] + ga.y, c0[0] + ga.x);
        unsigned u1 = cvt_bf2(c1[1] + gb2.y, c1[0] + gb2.x);
        asm volatile("st.shared::cluster.u32 [%0],%1;" :: "r"(dst0), "r"(u0) : "memory");
        asm volatile("st.shared::cluster.u32 [%0],%1;" :: "r"(dst0 + 16), "r"(u1) : "memory");
        __syncthreads();
        if (tid == 0) {
#pragma unroll
            for (int r = 0; r < 4; r++)
                if (r != (int)rank)
                    asm volatile("mbarrier.arrive.release.cluster.shared::cluster.b64 _, [%0];"
                                 :: "r"(rb1[r]) : "memory");
        }
        {
            unsigned ph = (unsigned)step & 1u;
            MBAR_WAIT(b1_l, ph);
        }

        // ---- cell update for own 2 batch rows (preacts already include gx) ----
        float pi = bfhalf(rcv[0],   hlf);
        float pf = bfhalf(rcv[256], hlf);
        float pg = bfhalf(rcv[512], hlf);
        float po = bfhalf(rcv[768], hlf);
        float i_ = sigt(pi), f_ = sigt(pf), g_ = tanha(pg), o_ = sigt(po);
        cc = f_ * cc + i_ * g_;
        float hv = o_ * tanha(cc);

        // ---- broadcast new h row to all 4 CTAs + paired hcat store ----
        float hn = __shfl_down_sync(0xffffffffu, hv, 1);
        if (!hlf) {
            unsigned hu = cvt_bf2(hn, hv);
            unsigned off = (unsigned)(buf ^ 1) * HBUFB + (unsigned)hrow * HPITCH + (unsigned)j * 2;
#pragma unroll
            for (int r = 0; r < 4; r++)
                asm volatile("st.shared::cluster.u32 [%0],%1;" :: "r"(rh[r] + off), "r"(hu) : "memory");
            *(float2*)(d_hcat + ((size_t)b_own * 512 + l) * 512 + dir * 256 + j) =
                make_float2(hv, hn);
        }
        __syncthreads();
        if (tid == 0) {
#pragma unroll
            for (int r = 0; r < 4; r++)
                if (r != (int)rank)
                    asm volatile("mbarrier.arrive.release.cluster.shared::cluster.b64 _, [%0];"
                                 :: "r"(rb2[r]) : "memory");
        }
        // producer gx prefetch for next step (into wait-2 shadow)
        if (step < 511) {
            int ln = dir ? (510 - step) : (step + 1);
            gxp = gxb + (size_t)(ln * 128 + b0 + bE) * 1024 + (int)rank * 256 + nl;
            ga = *(const float2*)gxp;
            gb2 = *(const float2*)(gxp + 8);
        }
        {
            unsigned ph = (unsigned)step & 1u;
            MBAR_WAIT(b2_l, ph);
        }
        buf ^= 1;
    }

    asm volatile("barrier.cluster.arrive.aligned;" ::: "memory");
    asm volatile("barrier.cluster.wait.aligned;" ::: "memory");
}

// ---------------- K3: emission = hcat @ w_cls^T + b_cls ----------------
__global__ void __launch_bounds__(256) k_emis(const float* __restrict__ wcls,
                                              const float* __restrict__ bcls) {
    __shared__ float wc[16 * 512];
    int tid = threadIdx.x;
    for (int i = tid; i < 16 * 512 / 4; i += 256)
        ((float4*)wc)[i] = ((const float4*)wcls)[i];
    __syncthreads();
    int m = blockIdx.x * 8 + (tid >> 5);
    int lane = tid & 31;
    float acc[16];
#pragma unroll
    for (int t = 0; t < 16; t++) acc[t] = 0.f;
    const float* hp = d_hcat + (size_t)m * 512;
#pragma unroll
    for (int it = 0; it < 4; it++) {
        int k = it * 128 + lane * 4;
        float4 h4 = *(const float4*)(hp + k);
#pragma unroll
        for (int t = 0; t < 16; t++) {
            float4 w4 = *(const float4*)(wc + t * 512 + k);
            acc[t] += h4.x * w4.x + h4.y * w4.y + h4.z * w4.z + h4.w * w4.w;
        }
    }
#pragma unroll
    for (int t = 0; t < 16; t++)
#pragma unroll
        for (int off = 16; off; off >>= 1) acc[t] += __shfl_xor_sync(0xffffffffu, acc[t], off);
    if (lane < 16) {
        float v = acc[0];
#pragma unroll
        for (int t = 1; t < 16; t++) v = (lane == t) ? acc[t] : v;
        d_emission[(size_t)m * 16 + lane] = v + bcls[lane];
    }
}

// ---------------- K4: CRF golden + forward (1 warp / batch row) ----------------
__global__ void k_crf(const int* __restrict__ tag, const float* __restrict__ trans) {
    __shared__ float tr[256];
    int b = blockIdx.x, lane = threadIdx.x;
    for (int i = lane; i < 256; i += 32) tr[i] = trans[i];
    __syncwarp();
    int cur = lane & 15;
    float tcol[16];
#pragma unroll
    for (int p = 0; p < 16; p++) tcol[p] = tr[p * 16 + cur];
    const int* tg = tag + b * 512;
    int len = 0;
    for (int l2 = lane; l2 < 512; l2 += 32) len += (tg[l2] != 0);
#pragma unroll
    for (int off = 16; off; off >>= 1) len += __shfl_xor_sync(0xffffffffu, len, off);

    const float* em = d_emission + (size_t)b * 512 * 16;
    float gsum = 0.f;
    for (int l2 = lane; l2 < 512; l2 += 32)
        if (l2 < len) {
            int t = tg[l2];
            int pv = l2 ? tg[l2 - 1] : 14;       // START=14
            gsum += em[l2 * 16 + t] + tr[pv * 16 + t];
        }
#pragma unroll
    for (int off = 16; off; off >>= 1) gsum += __shfl_xor_sync(0xffffffffu, gsum, off);

    float score = em[cur] + tr[14 * 16 + cur];
    for (int t = 1; t < 512; t++) {
        float v[16];
#pragma unroll
        for (int p = 0; p < 16; p++)
            v[p] = __shfl_sync(0xffffffffu, score, p) + tcol[p];
        float m0 = fmaxf(fmaxf(v[0], v[1]), fmaxf(v[2], v[3]));
        float m1 = fmaxf(fmaxf(v[4], v[5]), fmaxf(v[6], v[7]));
        float m2 = fmaxf(fmaxf(v[8], v[9]), fmaxf(v[10], v[11]));
        float m3 = fmaxf(fmaxf(v[12], v[13]), fmaxf(v[14], v[15]));
        float m = fmaxf(fmaxf(m0, m1), fmaxf(m2, m3));
        float e[16];
#pragma unroll
        for (int p = 0; p < 16; p++) e[p] = __expf(v[p] - m);
        float s0 = (e[0] + e[1]) + (e[2] + e[3]);
        float s1 = (e[4] + e[5]) + (e[6] + e[7]);
        float s2 = (e[8] + e[9]) + (e[10] + e[11]);
        float s3 = (e[12] + e[13]) + (e[14] + e[15]);
        float s = (s0 + s1) + (s2 + s3);
        float ns = em[t * 16 + cur] + m + __logf(s);
        score = (t < len) ? ns : score;
    }
    if (lane == 15) atomicAdd(&d_acc[0], (double)score);  // END=15
    if (lane == 0)  atomicAdd(&d_acc[1], (double)gsum);
}

__global__ void k_final(float* out) {
    out[0] = (float)((d_acc[0] - d_acc[1]) / 128.0);
}

// ---------------- launch ----------------
extern "C" void kernel_launch(void* const* d_in, const int* in_sizes, int n_in,
                              void* d_out, int out_size) {
    const int*   batch_data = (const int*)d_in[0];
    const int*   batch_tag  = (const int*)d_in[1];
    const float* emb        = (const float*)d_in[2];
    const float* w_ih_f     = (const float*)d_in[3];
    const float* w_hh_f     = (const float*)d_in[4];
    const float* b_f        = (const float*)d_in[5];
    const float* w_ih_b     = (const float*)d_in[6];
    const float* w_hh_b     = (const float*)d_in[7];
    const float* b_b        = (const float*)d_in[8];
    const float* w_cls      = (const float*)d_in[9];
    const float* b_cls      = (const float*)d_in[10];
    const float* transition = (const float*)d_in[11];

    cudaFuncSetAttribute(k_recur, cudaFuncAttributeMaxDynamicSharedMemorySize, SMEM_R);
    cudaFuncSetAttribute(k_gemm, cudaFuncAttributeMaxDynamicSharedMemorySize, GSM);

    k_prep<<<512, 256>>>(w_hh_f, w_hh_b, w_ih_f, w_ih_b);
    k_gather<<<8192, 256>>>(batch_data, emb);
    k_gemm<<<dim3(512, 16), 256, GSM>>>(b_f, b_b);
    k_recur<<<128, 512, SMEM_R>>>();
    k_emis<<<8192, 256>>>(w_cls, b_cls);
    k_crf<<<128, 32>>>(batch_tag, transition);
    k_final<<<1, 1>>>((float*)d_out);
}